// round 6
// baseline (speedup 1.0000x reference)
#include <cuda_runtime.h>
#include <math.h>

typedef unsigned long long ull;

#define BATCH 256
#define SEQ   128
#define VOCAB 512
#define GH    128
#define K0    65536
#define N0    1024
#define SPLITS 16
#define KC    (K0/SPLITS)

#define OFF_MU (BATCH*SEQ*VOCAB)          /* 16777216 */
#define OFF_LV (OFF_MU + BATCH*GH)        /* 16809984 */

// ---- scratch layout inside one __device__ array (no allocations) ----
#define S_WS     0u                        /* 16 x 256 x 1024  split-K partials */
#define S_H0     (S_WS + 4194304u)         /* 256x1024 */
#define S_H1     (S_H0 + 262144u)          /* 256x512  */
#define S_H2B    (S_H1 + 131072u)          /* 256x256  */
#define S_HENC   (S_H2B + 65536u)          /* 256x128  */
#define S_MU     (S_HENC + 32768u)
#define S_LV     (S_MU + 32768u)
#define S_Z      (S_LV + 32768u)
#define S_XP     (S_Z + 32768u)            /* 256x384  */
#define S_H2ALL  (S_XP + 98304u)           /* 32768x128 */
#define S_LOGITS (S_H2ALL + 4194304u)      /* 32768x512 */
#define S_SCALE  (S_LOGITS + 16777216u)    /* 1024 */
#define S_SHIFT  (S_SCALE + 1024u)         /* 1024 */
#define S_TOTAL  (S_SHIFT + 1024u)

__device__ float g_scratch[S_TOTAL];

// ---- packed fp32x2 helpers (Blackwell packed-FP32 pipe; PTX-only) ----
__device__ __forceinline__ void fma2(ull &d, ull a, ull b) {
    asm("fma.rn.f32x2 %0, %1, %2, %0;" : "+l"(d) : "l"(a), "l"(b));
}
__device__ __forceinline__ ull pk2(float x, float y) {
    ull d; asm("mov.b64 %0, {%1, %2};" : "=l"(d) : "f"(x), "f"(y)); return d;
}
__device__ __forceinline__ float2 unpk2(ull d) {
    float2 r; asm("mov.b64 {%0, %1}, %2;" : "=f"(r.x), "=f"(r.y) : "l"(d)); return r;
}

// ============================================================================
// GEMM0: ws[split] = X[256,65536] @ W0[1024,65536]^T   (split-K partials)
// BM=128 BN=64 BK=32, 256 threads, thread tile 4x8 via f32x2
// ============================================================================
__global__ __launch_bounds__(256) void gemm0_kernel(const float* __restrict__ X,
                                                    const float* __restrict__ W,
                                                    float* __restrict__ ws) {
    __shared__ float As[32][132];
    __shared__ float Bs[32][68];
    const int tid   = threadIdx.x;
    const int n0    = blockIdx.x * 64;
    const int m0    = blockIdx.y * 128;
    const int kbase = blockIdx.z * KC;
    const int trow  = tid >> 3;   // 0..31 -> 4 rows each
    const int tcol  = tid & 7;    // 0..7  -> 8 cols each

    ull acc[4][4];
    #pragma unroll
    for (int r = 0; r < 4; r++)
        #pragma unroll
        for (int q = 0; q < 4; q++) acc[r][q] = 0ull;

    for (int kk = 0; kk < KC; kk += 32) {
        #pragma unroll
        for (int i = 0; i < 4; i++) {
            int f = tid + i * 256;             // A tile 128x32
            int m = f >> 3, kq = f & 7;
            float4 v = *(const float4*)&X[(size_t)(m0 + m) * K0 + kbase + kk + kq * 4];
            As[kq*4+0][m] = v.x; As[kq*4+1][m] = v.y;
            As[kq*4+2][m] = v.z; As[kq*4+3][m] = v.w;
        }
        #pragma unroll
        for (int i = 0; i < 2; i++) {
            int f = tid + i * 256;             // B tile 64x32
            int n = f >> 3, kq = f & 7;
            float4 v = *(const float4*)&W[(size_t)(n0 + n) * K0 + kbase + kk + kq * 4];
            Bs[kq*4+0][n] = v.x; Bs[kq*4+1][n] = v.y;
            Bs[kq*4+2][n] = v.z; Bs[kq*4+3][n] = v.w;
        }
        __syncthreads();

        #pragma unroll 8
        for (int k = 0; k < 32; k++) {
            float4 a = *(const float4*)&As[k][trow * 4];
            const ull* bp = (const ull*)&Bs[k][tcol * 8];
            ull bd0 = bp[0], bd1 = bp[1], bd2 = bp[2], bd3 = bp[3];
            ull ad0 = pk2(a.x, a.x), ad1 = pk2(a.y, a.y);
            ull ad2 = pk2(a.z, a.z), ad3 = pk2(a.w, a.w);
            fma2(acc[0][0], ad0, bd0); fma2(acc[0][1], ad0, bd1);
            fma2(acc[0][2], ad0, bd2); fma2(acc[0][3], ad0, bd3);
            fma2(acc[1][0], ad1, bd0); fma2(acc[1][1], ad1, bd1);
            fma2(acc[1][2], ad1, bd2); fma2(acc[1][3], ad1, bd3);
            fma2(acc[2][0], ad2, bd0); fma2(acc[2][1], ad2, bd1);
            fma2(acc[2][2], ad2, bd2); fma2(acc[2][3], ad2, bd3);
            fma2(acc[3][0], ad3, bd0); fma2(acc[3][1], ad3, bd1);
            fma2(acc[3][2], ad3, bd2); fma2(acc[3][3], ad3, bd3);
        }
        __syncthreads();
    }

    float* wsp = ws + (size_t)blockIdx.z * (BATCH * N0);
    #pragma unroll
    for (int r = 0; r < 4; r++) {
        int m = m0 + trow * 4 + r;
        float* dst = wsp + (size_t)m * N0 + n0 + tcol * 8;
        #pragma unroll
        for (int q = 0; q < 4; q++) {
            float2 v = unpk2(acc[r][q]);
            dst[q*2] = v.x; dst[q*2+1] = v.y;
        }
    }
}

// deterministic split-K reduce + bias
__global__ __launch_bounds__(256) void reduce_bias_kernel(const float* __restrict__ ws,
                                                          const float* __restrict__ bias,
                                                          float* __restrict__ out) {
    int i = blockIdx.x * 256 + threadIdx.x;   // < 262144
    float s = 0.0f;
    #pragma unroll
    for (int sp = 0; sp < SPLITS; sp++) s += ws[(size_t)sp * (BATCH * N0) + i];
    out[i] = s + bias[i & (N0 - 1)];
}

// ============================================================================
// BatchNorm (2-pass) + LeakyReLU
// ============================================================================
__global__ void bn_stats_kernel(const float* __restrict__ h, const float* __restrict__ g,
                                const float* __restrict__ be, float* __restrict__ scale,
                                float* __restrict__ shift, int N) {
    int f = blockIdx.x * 256 + threadIdx.x;
    if (f >= N) return;
    float s = 0.f, ss = 0.f;
    #pragma unroll 4
    for (int b = 0; b < BATCH; b++) {
        float v = h[(size_t)b * N + f];
        s += v; ss += v * v;
    }
    float mean = s * (1.0f / BATCH);
    float var = ss * (1.0f / BATCH) - mean * mean;
    float sc = rsqrtf(var + 1e-5f) * g[f];
    scale[f] = sc;
    shift[f] = be[f] - mean * sc;
}

__global__ void bn_apply_kernel(float* __restrict__ h, const float* __restrict__ scale,
                                const float* __restrict__ shift, int nmask) {
    int i = blockIdx.x * 256 + threadIdx.x;
    int f = i & nmask;
    float o = h[i] * scale[f] + shift[f];
    h[i] = o > 0.f ? o : 0.01f * o;
}

// ============================================================================
// Generic fp32x2 GEMM: C[M,N] = act(A[M,K] @ W[N,K]^T + bias)
// BM=64 BN=64 BK=16, 256 threads, 4x4 thread tile. M,N % 64 == 0, K % 16 == 0.
// ============================================================================
__global__ __launch_bounds__(256) void gemm_kernel(const float* __restrict__ A,
        const float* __restrict__ W, const float* __restrict__ bias,
        float* __restrict__ C, int M, int N, int K, int act) {
    __shared__ float As[16][68];
    __shared__ float Bs[16][68];
    const int tid = threadIdx.x;
    const int n0 = blockIdx.x * 64;
    const int m0 = blockIdx.y * 64;
    const int trow = tid >> 4;        // 0..15
    const int tcol = tid & 15;        // 0..15
    const int lm = tid >> 2;          // 0..63
    const int lk = (tid & 3) * 4;     // 0,4,8,12

    ull acc[4][2];
    #pragma unroll
    for (int r = 0; r < 4; r++) { acc[r][0] = 0ull; acc[r][1] = 0ull; }

    for (int kk = 0; kk < K; kk += 16) {
        float4 va = *(const float4*)&A[(size_t)(m0 + lm) * K + kk + lk];
        float4 vb = *(const float4*)&W[(size_t)(n0 + lm) * K + kk + lk];
        As[lk+0][lm] = va.x; As[lk+1][lm] = va.y; As[lk+2][lm] = va.z; As[lk+3][lm] = va.w;
        Bs[lk+0][lm] = vb.x; Bs[lk+1][lm] = vb.y; Bs[lk+2][lm] = vb.z; Bs[lk+3][lm] = vb.w;
        __syncthreads();
        #pragma unroll
        for (int k = 0; k < 16; k++) {
            float4 a = *(const float4*)&As[k][trow * 4];
            const ull* bp = (const ull*)&Bs[k][tcol * 4];
            ull b0 = bp[0], b1 = bp[1];
            ull a0 = pk2(a.x, a.x), a1 = pk2(a.y, a.y);
            ull a2 = pk2(a.z, a.z), a3 = pk2(a.w, a.w);
            fma2(acc[0][0], a0, b0); fma2(acc[0][1], a0, b1);
            fma2(acc[1][0], a1, b0); fma2(acc[1][1], a1, b1);
            fma2(acc[2][0], a2, b0); fma2(acc[2][1], a2, b1);
            fma2(acc[3][0], a3, b0); fma2(acc[3][1], a3, b1);
        }
        __syncthreads();
    }

    #pragma unroll
    for (int r = 0; r < 4; r++) {
        int m = m0 + trow * 4 + r;
        int n = n0 + tcol * 4;
        float2 v0 = unpk2(acc[r][0]);
        float2 v1 = unpk2(acc[r][1]);
        float o0 = v0.x + bias[n+0];
        float o1 = v0.y + bias[n+1];
        float o2 = v1.x + bias[n+2];
        float o3 = v1.y + bias[n+3];
        if (act == 1) {
            o0 = fmaxf(o0, 0.f); o1 = fmaxf(o1, 0.f);
            o2 = fmaxf(o2, 0.f); o3 = fmaxf(o3, 0.f);
        }
        float4 ov = make_float4(o0, o1, o2, o3);
        *(float4*)&C[(size_t)m * N + n] = ov;
    }
}

// ============================================================================
// reparameterize + emit mu/logvar to output tail
// ============================================================================
__global__ void reparam_kernel(const float* __restrict__ mu, const float* __restrict__ lv,
                               const float* __restrict__ eps, float* __restrict__ z,
                               float* __restrict__ out) {
    int i = blockIdx.x * 256 + threadIdx.x;  // < 32768
    float m = mu[i], l = lv[i];
    z[i] = m + eps[i] * expf(0.5f * l);
    out[OFF_MU + i] = m;
    out[OFF_LV + i] = l;
}

// ============================================================================
// GRU recurrence: 128 blocks x 384 threads, 2 batch rows per block,
// Whh packed-transposed in 192 KB smem. Writes all h_t to h2all[t*256+b][128].
// ============================================================================
#define GRU_SMEM 205312
__global__ __launch_bounds__(384, 1) void gru_kernel(const float* __restrict__ xp,
        const float* __restrict__ Whh, const float* __restrict__ bhh,
        float* __restrict__ h2all) {
    extern __shared__ float sm[];
    float4* whh4 = (float4*)sm;            // [32][384] float4
    float* h_s   = sm + 49152;             // [2][128]
    float* hp_s  = sm + 49152 + 256;       // [2][384]
    float* xp_s  = sm + 49152 + 1024;      // [2][384]
    float* bhh_s = sm + 49152 + 1792;      // [384]
    const int j = threadIdx.x;             // 0..383 (gate-unit)
    const int row0 = blockIdx.x * 2;

    #pragma unroll 4
    for (int kq = 0; kq < 32; kq++)
        whh4[kq * 384 + j] = *(const float4*)&Whh[(size_t)j * GH + kq * 4];
    bhh_s[j] = bhh[j];
    xp_s[j]       = xp[(size_t)row0 * 384 + j];
    xp_s[384 + j] = xp[(size_t)(row0 + 1) * 384 + j];
    if (j < 256) h_s[j] = 0.0f;
    __syncthreads();

    for (int t = 0; t < SEQ; t++) {
        float acc0 = 0.f, acc1 = 0.f;
        const float4* wp = whh4 + j;
        #pragma unroll 8
        for (int kq = 0; kq < 32; kq++) {
            float4 w  = wp[kq * 384];
            float4 ha = *(const float4*)&h_s[kq * 4];
            float4 hb = *(const float4*)&h_s[128 + kq * 4];
            acc0 += w.x*ha.x + w.y*ha.y + w.z*ha.z + w.w*ha.w;
            acc1 += w.x*hb.x + w.y*hb.y + w.z*hb.z + w.w*hb.w;
        }
        hp_s[j]       = acc0 + bhh_s[j];
        hp_s[384 + j] = acc1 + bhh_s[j];
        __syncthreads();
        if (j < 256) {
            int r = j >> 7, u = j & 127;
            const float* hp = hp_s + r * 384;
            const float* xq = xp_s + r * 384;
            float rg = 1.0f / (1.0f + expf(-(xq[u]       + hp[u])));
            float zg = 1.0f / (1.0f + expf(-(xq[128 + u] + hp[128 + u])));
            float nn = tanhf(xq[256 + u] + rg * hp[256 + u]);
            float hold = h_s[r * 128 + u];
            float hnew = (1.0f - zg) * nn + zg * hold;
            h_s[r * 128 + u] = hnew;
            h2all[((size_t)t * BATCH + row0 + r) * GH + u] = hnew;
        }
        __syncthreads();
    }
}

// ============================================================================
// argmax + one-hot: warp per row (row = t*256 + b), writes out[b][t][:]
// ============================================================================
__global__ __launch_bounds__(256) void argmax_onehot_kernel(const float* __restrict__ logits,
                                                            float* __restrict__ out) {
    int row  = blockIdx.x * 8 + (threadIdx.x >> 5);   // < 32768
    int lane = threadIdx.x & 31;
    const float* lp = logits + (size_t)row * VOCAB;
    float best = -1e30f; int bi = 0;
    #pragma unroll
    for (int q = 0; q < 16; q++) {
        int c = lane + q * 32;
        float v = lp[c];
        if (v > best) { best = v; bi = c; }
    }
    #pragma unroll
    for (int o = 16; o > 0; o >>= 1) {
        float ov = __shfl_down_sync(0xffffffffu, best, o);
        int   oi = __shfl_down_sync(0xffffffffu, bi, o);
        if (ov > best || (ov == best && oi < bi)) { best = ov; bi = oi; }
    }
    bi = __shfl_sync(0xffffffffu, bi, 0);
    int t = row >> 8, b = row & 255;
    float* op = out + (size_t)b * (SEQ * VOCAB) + (size_t)t * VOCAB;
    #pragma unroll
    for (int q = 0; q < 4; q++) {
        int c = lane * 16 + q * 4;
        float4 v = make_float4(c == bi ? 1.f : 0.f, c + 1 == bi ? 1.f : 0.f,
                               c + 2 == bi ? 1.f : 0.f, c + 3 == bi ? 1.f : 0.f);
        *(float4*)&op[c] = v;
    }
}

// ============================================================================
// launcher
// ============================================================================
extern "C" void kernel_launch(void* const* d_in, const int* in_sizes, int n_in,
                              void* d_out, int out_size) {
    (void)in_sizes; (void)n_in; (void)out_size;
    const float* x    = (const float*)d_in[0];
    const float* eps  = (const float*)d_in[1];
    const float* W0   = (const float*)d_in[2];
    const float* b0   = (const float*)d_in[3];
    const float* g0   = (const float*)d_in[4];
    const float* be0  = (const float*)d_in[5];
    const float* W1   = (const float*)d_in[6];
    const float* b1   = (const float*)d_in[7];
    const float* g1   = (const float*)d_in[8];
    const float* be1  = (const float*)d_in[9];
    const float* W2   = (const float*)d_in[10];
    const float* b2   = (const float*)d_in[11];
    const float* g2   = (const float*)d_in[12];
    const float* be2  = (const float*)d_in[13];
    const float* Wout = (const float*)d_in[14];
    const float* bout = (const float*)d_in[15];
    const float* Wmu  = (const float*)d_in[16];
    const float* bmu  = (const float*)d_in[17];
    const float* Wlv  = (const float*)d_in[18];
    const float* blv  = (const float*)d_in[19];
    const float* Wih  = (const float*)d_in[20];
    const float* bih  = (const float*)d_in[21];
    const float* Whh  = (const float*)d_in[22];
    const float* bhh  = (const float*)d_in[23];
    const float* Wfc  = (const float*)d_in[24];
    const float* bfc  = (const float*)d_in[25];
    float* out = (float*)d_out;

    float* S = nullptr;
    cudaGetSymbolAddress((void**)&S, g_scratch);

    cudaFuncSetAttribute(gru_kernel, cudaFuncAttributeMaxDynamicSharedMemorySize, GRU_SMEM);

    // --- encoder layer 0 (big GEMM, split-K) ---
    gemm0_kernel<<<dim3(16, 2, SPLITS), 256>>>(x, W0, S + S_WS);
    reduce_bias_kernel<<<1024, 256>>>(S + S_WS, b0, S + S_H0);
    bn_stats_kernel<<<4, 256>>>(S + S_H0, g0, be0, S + S_SCALE, S + S_SHIFT, 1024);
    bn_apply_kernel<<<1024, 256>>>(S + S_H0, S + S_SCALE, S + S_SHIFT, 1023);

    // --- encoder layer 1: 1024 -> 512 ---
    gemm_kernel<<<dim3(8, 4), 256>>>(S + S_H0, W1, b1, S + S_H1, 256, 512, 1024, 0);
    bn_stats_kernel<<<2, 256>>>(S + S_H1, g1, be1, S + S_SCALE, S + S_SHIFT, 512);
    bn_apply_kernel<<<512, 256>>>(S + S_H1, S + S_SCALE, S + S_SHIFT, 511);

    // --- encoder layer 2: 512 -> 256 ---
    gemm_kernel<<<dim3(4, 4), 256>>>(S + S_H1, W2, b2, S + S_H2B, 256, 256, 512, 0);
    bn_stats_kernel<<<1, 256>>>(S + S_H2B, g2, be2, S + S_SCALE, S + S_SHIFT, 256);
    bn_apply_kernel<<<256, 256>>>(S + S_H2B, S + S_SCALE, S + S_SHIFT, 255);

    // --- out layer (relu), mu, logvar ---
    gemm_kernel<<<dim3(2, 4), 256>>>(S + S_H2B, Wout, bout, S + S_HENC, 256, 128, 256, 1);
    gemm_kernel<<<dim3(2, 4), 256>>>(S + S_HENC, Wmu, bmu, S + S_MU, 256, 128, 128, 0);
    gemm_kernel<<<dim3(2, 4), 256>>>(S + S_HENC, Wlv, blv, S + S_LV, 256, 128, 128, 0);

    // --- reparameterize (also writes mu/logvar outputs) ---
    reparam_kernel<<<128, 256>>>(S + S_MU, S + S_LV, eps, S + S_Z, out);

    // --- GRU input projection (constant per step) ---
    gemm_kernel<<<dim3(6, 4), 256>>>(S + S_Z, Wih, bih, S + S_XP, 256, 384, 128, 0);

    // --- GRU recurrence (persistent, single wave) ---
    gru_kernel<<<128, 384, GRU_SMEM>>>(S + S_XP, Whh, bhh, S + S_H2ALL);

    // --- logits for all (t, b) at once, then argmax/one-hot ---
    gemm_kernel<<<dim3(8, 512), 256>>>(S + S_H2ALL, Wfc, bfc, S + S_LOGITS,
                                       32768, 512, 128, 0);
    argmax_onehot_kernel<<<4096, 256>>>(S + S_LOGITS, out);
}

// round 8
// speedup vs baseline: 1.8149x; 1.8149x over previous
#include <cuda_runtime.h>
#include <math.h>
#include <stdint.h>

typedef unsigned long long ull;

#define BATCH 256
#define SEQ   128
#define VOCAB 512
#define GH    128
#define K0    65536
#define N0    1024
#define GSPLITS 16
#define GKC   (K0/GSPLITS)   /* 4096 */

#define OFF_MU (BATCH*SEQ*VOCAB)
#define OFF_LV (OFF_MU + BATCH*GH)

// ---- scratch layout (single static __device__ array) ----
#define S_WS     0u                        /* 16 x 256 x 1024 split-K partials */
#define S_H0     (S_WS + 4194304u)         /* 256x1024 */
#define S_H1     (S_H0 + 262144u)          /* 256x512  */
#define S_H2B    (S_H1 + 131072u)          /* 256x256  */
#define S_HENC   (S_H2B + 65536u)          /* 256x128  */
#define S_MU     (S_HENC + 32768u)
#define S_LV     (S_MU + 32768u)
#define S_Z      (S_LV + 32768u)
#define S_XP     (S_Z + 32768u)            /* 256x384  */
#define S_H2ALL  (S_XP + 98304u)           /* 32768x128 */
#define S_LOGITS (S_H2ALL + 4194304u)      /* 32768x512 */
#define S_SCALE  (S_LOGITS + 16777216u)
#define S_SHIFT  (S_SCALE + 1024u)
#define S_TOTAL  (S_SHIFT + 1024u)

__device__ float g_scratch[S_TOTAL];

// ============================================================================
// TF32 helpers (baseline PTX — works on plain sm_103 target)
// ============================================================================
__device__ __forceinline__ uint32_t cvt_tf32(float x) {
    uint32_t r; asm("cvt.rna.tf32.f32 %0, %1;" : "=r"(r) : "f"(x)); return r;
}

#define MMA_TF32(acc, af, bf) asm volatile( \
    "mma.sync.aligned.m16n8k8.row.col.f32.tf32.tf32.f32 " \
    "{%0,%1,%2,%3}, {%4,%5,%6,%7}, {%8,%9}, {%0,%1,%2,%3};" \
    : "+f"((acc)[0]), "+f"((acc)[1]), "+f"((acc)[2]), "+f"((acc)[3]) \
    : "r"((af)[0]), "r"((af)[1]), "r"((af)[2]), "r"((af)[3]), \
      "r"((bf)[0]), "r"((bf)[1]))

// smem plane layout: rows padded to stride 36 floats (bank = 4g+t, conflict-free)
#define PSTRIDE 36
#define PLANE   (128 * PSTRIDE)            /* 4608 floats */
#define BUFSTR  (4 * PLANE)                /* 18432 floats per buffer */
#define MMA_SMEM (2 * BUFSTR * 4)          /* 147456 bytes */

// ============================================================================
// TF32x3 tensor-core GEMM via mma.sync:
//   C[m0..m0+127, n0..n0+127] (+)= A[m,kbase..] @ B[n,kbase..]^T
//   A: [M,ldA] row-major fp32; B: [N,ldA] row-major fp32 (weights)
//   bias != null  -> direct write C[row*ldc+col] = acc + bias[col]
//   bias == null  -> write partials to C + blockIdx.z*splitStride
// ============================================================================
__global__ __launch_bounds__(256, 1) void gemm_mma(const float* __restrict__ A,
        const float* __restrict__ B, const float* __restrict__ bias,
        float* __restrict__ C, int ldA, int ldc, int nchunks, int kc,
        size_t splitStride) {
    extern __shared__ float smf[];
    const int tid  = threadIdx.x;
    const int lane = tid & 31;
    const int g    = lane >> 2;       // 0..7
    const int t    = lane & 3;        // 0..3
    const int warp = tid >> 5;
    const int m0w  = (warp >> 2) * 64;   // 0 or 64
    const int n0w  = (warp & 3) * 32;    // 0,32,64,96
    const int n0   = blockIdx.x * 128;
    const int m0   = blockIdx.y * 128;
    const int kbase = blockIdx.z * kc;

    const int rb = tid >> 3;          // 0..31
    const int q  = tid & 7;           // 0..7

    float acc[4][4][4];
    #pragma unroll
    for (int mt = 0; mt < 4; mt++)
        #pragma unroll
        for (int nt = 0; nt < 4; nt++)
            #pragma unroll
            for (int i = 0; i < 4; i++) acc[mt][nt][i] = 0.0f;

    float4 stA[4], stB[4];

    // prologue: stage chunk 0
    #pragma unroll
    for (int j = 0; j < 4; j++) {
        stA[j] = *(const float4*)&A[(size_t)(m0 + rb + 32*j) * ldA + kbase + q*4];
        stB[j] = *(const float4*)&B[(size_t)(n0 + rb + 32*j) * ldA + kbase + q*4];
    }
    {
        float* buf = smf;
        uint32_t* ahi = (uint32_t*)buf;
        uint32_t* alo = (uint32_t*)(buf + PLANE);
        uint32_t* bhi = (uint32_t*)(buf + 2*PLANE);
        uint32_t* blo = (uint32_t*)(buf + 3*PLANE);
        #pragma unroll
        for (int j = 0; j < 4; j++) {
            int off = (rb + 32*j) * PSTRIDE + q*4;
            float4 v = stA[j];
            uint32_t hx=cvt_tf32(v.x), hy=cvt_tf32(v.y), hz=cvt_tf32(v.z), hw=cvt_tf32(v.w);
            *(uint4*)&ahi[off] = make_uint4(hx,hy,hz,hw);
            *(uint4*)&alo[off] = make_uint4(
                cvt_tf32(v.x-__uint_as_float(hx)), cvt_tf32(v.y-__uint_as_float(hy)),
                cvt_tf32(v.z-__uint_as_float(hz)), cvt_tf32(v.w-__uint_as_float(hw)));
            v = stB[j];
            hx=cvt_tf32(v.x); hy=cvt_tf32(v.y); hz=cvt_tf32(v.z); hw=cvt_tf32(v.w);
            *(uint4*)&bhi[off] = make_uint4(hx,hy,hz,hw);
            *(uint4*)&blo[off] = make_uint4(
                cvt_tf32(v.x-__uint_as_float(hx)), cvt_tf32(v.y-__uint_as_float(hy)),
                cvt_tf32(v.z-__uint_as_float(hz)), cvt_tf32(v.w-__uint_as_float(hw)));
        }
    }
    __syncthreads();

    for (int c = 0; c < nchunks; c++) {
        // stage next chunk from gmem (overlaps with mma below)
        if (c + 1 < nchunks) {
            int kp = kbase + (c + 1) * 32;
            #pragma unroll
            for (int j = 0; j < 4; j++) {
                stA[j] = *(const float4*)&A[(size_t)(m0 + rb + 32*j) * ldA + kp + q*4];
                stB[j] = *(const float4*)&B[(size_t)(n0 + rb + 32*j) * ldA + kp + q*4];
            }
        }

        const uint32_t* base = (const uint32_t*)(smf + (c & 1) * BUFSTR);
        const uint32_t* pAhi = base;
        const uint32_t* pAlo = base + PLANE;
        const uint32_t* pBhi = base + 2*PLANE;
        const uint32_t* pBlo = base + 3*PLANE;

        #pragma unroll
        for (int ks = 0; ks < 4; ks++) {
            const int kk = ks * 8;
            uint32_t aHi[4][4], aLo[4][4], bHi[4][2], bLo[4][2];
            #pragma unroll
            for (int mt = 0; mt < 4; mt++) {
                int r0 = (m0w + mt*16 + g) * PSTRIDE + kk + t;
                aHi[mt][0] = pAhi[r0];
                aHi[mt][1] = pAhi[r0 + 8*PSTRIDE];
                aHi[mt][2] = pAhi[r0 + 4];
                aHi[mt][3] = pAhi[r0 + 8*PSTRIDE + 4];
                aLo[mt][0] = pAlo[r0];
                aLo[mt][1] = pAlo[r0 + 8*PSTRIDE];
                aLo[mt][2] = pAlo[r0 + 4];
                aLo[mt][3] = pAlo[r0 + 8*PSTRIDE + 4];
            }
            #pragma unroll
            for (int nt = 0; nt < 4; nt++) {
                int rn = (n0w + nt*8 + g) * PSTRIDE + kk + t;
                bHi[nt][0] = pBhi[rn];
                bHi[nt][1] = pBhi[rn + 4];
                bLo[nt][0] = pBlo[rn];
                bLo[nt][1] = pBlo[rn + 4];
            }
            #pragma unroll
            for (int mt = 0; mt < 4; mt++)
                #pragma unroll
                for (int nt = 0; nt < 4; nt++) {
                    MMA_TF32(acc[mt][nt], aHi[mt], bHi[nt]);
                    MMA_TF32(acc[mt][nt], aHi[mt], bLo[nt]);
                    MMA_TF32(acc[mt][nt], aLo[mt], bHi[nt]);
                }
        }

        // convert+store next chunk into the other buffer (its last reader was
        // chunk c-1, which finished before the sync that ended iteration c-1)
        if (c + 1 < nchunks) {
            float* buf = smf + ((c + 1) & 1) * BUFSTR;
            uint32_t* ahi = (uint32_t*)buf;
            uint32_t* alo = (uint32_t*)(buf + PLANE);
            uint32_t* bhi = (uint32_t*)(buf + 2*PLANE);
            uint32_t* blo = (uint32_t*)(buf + 3*PLANE);
            #pragma unroll
            for (int j = 0; j < 4; j++) {
                int off = (rb + 32*j) * PSTRIDE + q*4;
                float4 v = stA[j];
                uint32_t hx=cvt_tf32(v.x), hy=cvt_tf32(v.y), hz=cvt_tf32(v.z), hw=cvt_tf32(v.w);
                *(uint4*)&ahi[off] = make_uint4(hx,hy,hz,hw);
                *(uint4*)&alo[off] = make_uint4(
                    cvt_tf32(v.x-__uint_as_float(hx)), cvt_tf32(v.y-__uint_as_float(hy)),
                    cvt_tf32(v.z-__uint_as_float(hz)), cvt_tf32(v.w-__uint_as_float(hw)));
                v = stB[j];
                hx=cvt_tf32(v.x); hy=cvt_tf32(v.y); hz=cvt_tf32(v.z); hw=cvt_tf32(v.w);
                *(uint4*)&bhi[off] = make_uint4(hx,hy,hz,hw);
                *(uint4*)&blo[off] = make_uint4(
                    cvt_tf32(v.x-__uint_as_float(hx)), cvt_tf32(v.y-__uint_as_float(hy)),
                    cvt_tf32(v.z-__uint_as_float(hz)), cvt_tf32(v.w-__uint_as_float(hw)));
            }
        }
        __syncthreads();
    }

    // epilogue
    float* Cp = bias ? C : (C + (size_t)blockIdx.z * splitStride);
    #pragma unroll
    for (int mt = 0; mt < 4; mt++) {
        #pragma unroll
        for (int nt = 0; nt < 4; nt++) {
            int row = m0 + m0w + mt*16 + g;
            int col = n0 + n0w + nt*8 + 2*t;
            float2 v0 = make_float2(acc[mt][nt][0], acc[mt][nt][1]);
            float2 v1 = make_float2(acc[mt][nt][2], acc[mt][nt][3]);
            if (bias) {
                float bx = bias[col], by = bias[col+1];
                v0.x += bx; v0.y += by; v1.x += bx; v1.y += by;
            }
            *(float2*)&Cp[(size_t)row * ldc + col] = v0;
            *(float2*)&Cp[(size_t)(row + 8) * ldc + col] = v1;
        }
    }
}

// deterministic split-K reduce + bias (GEMM0)
__global__ __launch_bounds__(256) void reduce_bias_kernel(const float* __restrict__ ws,
                                                          const float* __restrict__ bias,
                                                          float* __restrict__ out) {
    int i = blockIdx.x * 256 + threadIdx.x;   // < 262144
    float s = 0.0f;
    #pragma unroll
    for (int sp = 0; sp < GSPLITS; sp++) s += ws[(size_t)sp * (BATCH * N0) + i];
    out[i] = s + bias[i & (N0 - 1)];
}

// ============================================================================
// BatchNorm (2-pass) + LeakyReLU
// ============================================================================
__global__ void bn_stats_kernel(const float* __restrict__ h, const float* __restrict__ g,
                                const float* __restrict__ be, float* __restrict__ scale,
                                float* __restrict__ shift, int N) {
    int f = blockIdx.x * 256 + threadIdx.x;
    if (f >= N) return;
    float s = 0.f, ss = 0.f;
    #pragma unroll 4
    for (int b = 0; b < BATCH; b++) {
        float v = h[(size_t)b * N + f];
        s += v; ss += v * v;
    }
    float mean = s * (1.0f / BATCH);
    float var = ss * (1.0f / BATCH) - mean * mean;
    float sc = rsqrtf(var + 1e-5f) * g[f];
    scale[f] = sc;
    shift[f] = be[f] - mean * sc;
}

__global__ void bn_apply_kernel(float* __restrict__ h, const float* __restrict__ scale,
                                const float* __restrict__ shift, int nmask) {
    int i = blockIdx.x * 256 + threadIdx.x;
    int f = i & nmask;
    float o = h[i] * scale[f] + shift[f];
    h[i] = o > 0.f ? o : 0.01f * o;
}

// ============================================================================
// Generic fp32x2 GEMM (small layers): C = act(A[M,K] @ W[N,K]^T + bias)
// ============================================================================
__device__ __forceinline__ void fma2(ull &d, ull a, ull b) {
    asm("fma.rn.f32x2 %0, %1, %2, %0;" : "+l"(d) : "l"(a), "l"(b));
}
__device__ __forceinline__ ull pk2(float x, float y) {
    ull d; asm("mov.b64 %0, {%1, %2};" : "=l"(d) : "f"(x), "f"(y)); return d;
}
__device__ __forceinline__ float2 unpk2(ull d) {
    float2 r; asm("mov.b64 {%0, %1}, %2;" : "=f"(r.x), "=f"(r.y) : "l"(d)); return r;
}

__global__ __launch_bounds__(256) void gemm_kernel(const float* __restrict__ A,
        const float* __restrict__ W, const float* __restrict__ bias,
        float* __restrict__ C, int M, int N, int K, int act) {
    __shared__ float As[16][68];
    __shared__ float Bs[16][68];
    const int tid = threadIdx.x;
    const int n0 = blockIdx.x * 64;
    const int m0 = blockIdx.y * 64;
    const int trow = tid >> 4;
    const int tcol = tid & 15;
    const int lm = tid >> 2;
    const int lk = (tid & 3) * 4;

    ull acc[4][2];
    #pragma unroll
    for (int r = 0; r < 4; r++) { acc[r][0] = 0ull; acc[r][1] = 0ull; }

    for (int kk = 0; kk < K; kk += 16) {
        float4 va = *(const float4*)&A[(size_t)(m0 + lm) * K + kk + lk];
        float4 vb = *(const float4*)&W[(size_t)(n0 + lm) * K + kk + lk];
        As[lk+0][lm] = va.x; As[lk+1][lm] = va.y; As[lk+2][lm] = va.z; As[lk+3][lm] = va.w;
        Bs[lk+0][lm] = vb.x; Bs[lk+1][lm] = vb.y; Bs[lk+2][lm] = vb.z; Bs[lk+3][lm] = vb.w;
        __syncthreads();
        #pragma unroll
        for (int k = 0; k < 16; k++) {
            float4 a = *(const float4*)&As[k][trow * 4];
            const ull* bp = (const ull*)&Bs[k][tcol * 4];
            ull b0 = bp[0], b1 = bp[1];
            ull a0 = pk2(a.x, a.x), a1 = pk2(a.y, a.y);
            ull a2 = pk2(a.z, a.z), a3 = pk2(a.w, a.w);
            fma2(acc[0][0], a0, b0); fma2(acc[0][1], a0, b1);
            fma2(acc[1][0], a1, b0); fma2(acc[1][1], a1, b1);
            fma2(acc[2][0], a2, b0); fma2(acc[2][1], a2, b1);
            fma2(acc[3][0], a3, b0); fma2(acc[3][1], a3, b1);
        }
        __syncthreads();
    }

    #pragma unroll
    for (int r = 0; r < 4; r++) {
        int m = m0 + trow * 4 + r;
        int n = n0 + tcol * 4;
        float2 v0 = unpk2(acc[r][0]);
        float2 v1 = unpk2(acc[r][1]);
        float o0 = v0.x + bias[n+0];
        float o1 = v0.y + bias[n+1];
        float o2 = v1.x + bias[n+2];
        float o3 = v1.y + bias[n+3];
        if (act == 1) {
            o0 = fmaxf(o0, 0.f); o1 = fmaxf(o1, 0.f);
            o2 = fmaxf(o2, 0.f); o3 = fmaxf(o3, 0.f);
        }
        *(float4*)&C[(size_t)m * N + n] = make_float4(o0, o1, o2, o3);
    }
}

// ============================================================================
// reparameterize + emit mu/logvar to output tail
// ============================================================================
__global__ void reparam_kernel(const float* __restrict__ mu, const float* __restrict__ lv,
                               const float* __restrict__ eps, float* __restrict__ z,
                               float* __restrict__ out) {
    int i = blockIdx.x * 256 + threadIdx.x;
    float m = mu[i], l = lv[i];
    z[i] = m + eps[i] * expf(0.5f * l);
    out[OFF_MU + i] = m;
    out[OFF_LV + i] = l;
}

// ============================================================================
// GRU recurrence (persistent, 128 CTAs x 384 thr, 2 rows/CTA)
// ============================================================================
#define GRU_SMEM 205312
__global__ __launch_bounds__(384, 1) void gru_kernel(const float* __restrict__ xp,
        const float* __restrict__ Whh, const float* __restrict__ bhh,
        float* __restrict__ h2all) {
    extern __shared__ float sm[];
    float4* whh4 = (float4*)sm;
    float* h_s   = sm + 49152;
    float* hp_s  = sm + 49152 + 256;
    float* xp_s  = sm + 49152 + 1024;
    float* bhh_s = sm + 49152 + 1792;
    const int j = threadIdx.x;
    const int row0 = blockIdx.x * 2;

    #pragma unroll 4
    for (int kq = 0; kq < 32; kq++)
        whh4[kq * 384 + j] = *(const float4*)&Whh[(size_t)j * GH + kq * 4];
    bhh_s[j] = bhh[j];
    xp_s[j]       = xp[(size_t)row0 * 384 + j];
    xp_s[384 + j] = xp[(size_t)(row0 + 1) * 384 + j];
    if (j < 256) h_s[j] = 0.0f;
    __syncthreads();

    for (int t = 0; t < SEQ; t++) {
        float acc0 = 0.f, acc1 = 0.f;
        const float4* wp = whh4 + j;
        #pragma unroll 8
        for (int kq = 0; kq < 32; kq++) {
            float4 w  = wp[kq * 384];
            float4 ha = *(const float4*)&h_s[kq * 4];
            float4 hb = *(const float4*)&h_s[128 + kq * 4];
            acc0 += w.x*ha.x + w.y*ha.y + w.z*ha.z + w.w*ha.w;
            acc1 += w.x*hb.x + w.y*hb.y + w.z*hb.z + w.w*hb.w;
        }
        hp_s[j]       = acc0 + bhh_s[j];
        hp_s[384 + j] = acc1 + bhh_s[j];
        __syncthreads();
        if (j < 256) {
            int r = j >> 7, u = j & 127;
            const float* hp = hp_s + r * 384;
            const float* xq = xp_s + r * 384;
            float rg = 1.0f / (1.0f + expf(-(xq[u]       + hp[u])));
            float zg = 1.0f / (1.0f + expf(-(xq[128 + u] + hp[128 + u])));
            float nn = tanhf(xq[256 + u] + rg * hp[256 + u]);
            float hold = h_s[r * 128 + u];
            float hnew = (1.0f - zg) * nn + zg * hold;
            h_s[r * 128 + u] = hnew;
            h2all[((size_t)t * BATCH + row0 + r) * GH + u] = hnew;
        }
        __syncthreads();
    }
}

// ============================================================================
// argmax + one-hot
// ============================================================================
__global__ __launch_bounds__(256) void argmax_onehot_kernel(const float* __restrict__ logits,
                                                            float* __restrict__ out) {
    int row  = blockIdx.x * 8 + (threadIdx.x >> 5);
    int lane = threadIdx.x & 31;
    const float* lp = logits + (size_t)row * VOCAB;
    float best = -1e30f; int bi = 0;
    #pragma unroll
    for (int q = 0; q < 16; q++) {
        int c = lane + q * 32;
        float v = lp[c];
        if (v > best) { best = v; bi = c; }
    }
    #pragma unroll
    for (int o = 16; o > 0; o >>= 1) {
        float ov = __shfl_down_sync(0xffffffffu, best, o);
        int   oi = __shfl_down_sync(0xffffffffu, bi, o);
        if (ov > best || (ov == best && oi < bi)) { best = ov; bi = oi; }
    }
    bi = __shfl_sync(0xffffffffu, bi, 0);
    int t = row >> 8, b = row & 255;
    float* op = out + (size_t)b * (SEQ * VOCAB) + (size_t)t * VOCAB;
    #pragma unroll
    for (int q = 0; q < 4; q++) {
        int c = lane * 16 + q * 4;
        *(float4*)&op[c] = make_float4(c == bi ? 1.f : 0.f, c + 1 == bi ? 1.f : 0.f,
                                       c + 2 == bi ? 1.f : 0.f, c + 3 == bi ? 1.f : 0.f);
    }
}

// ============================================================================
// launcher
// ============================================================================
extern "C" void kernel_launch(void* const* d_in, const int* in_sizes, int n_in,
                              void* d_out, int out_size) {
    (void)in_sizes; (void)n_in; (void)out_size;
    const float* x    = (const float*)d_in[0];
    const float* eps  = (const float*)d_in[1];
    const float* W0   = (const float*)d_in[2];
    const float* b0   = (const float*)d_in[3];
    const float* g0   = (const float*)d_in[4];
    const float* be0  = (const float*)d_in[5];
    const float* W1   = (const float*)d_in[6];
    const float* b1   = (const float*)d_in[7];
    const float* g1   = (const float*)d_in[8];
    const float* be1  = (const float*)d_in[9];
    const float* W2   = (const float*)d_in[10];
    const float* b2   = (const float*)d_in[11];
    const float* g2   = (const float*)d_in[12];
    const float* be2  = (const float*)d_in[13];
    const float* Wout = (const float*)d_in[14];
    const float* bout = (const float*)d_in[15];
    const float* Wmu  = (const float*)d_in[16];
    const float* bmu  = (const float*)d_in[17];
    const float* Wlv  = (const float*)d_in[18];
    const float* blv  = (const float*)d_in[19];
    const float* Wih  = (const float*)d_in[20];
    const float* bih  = (const float*)d_in[21];
    const float* Whh  = (const float*)d_in[22];
    const float* bhh  = (const float*)d_in[23];
    const float* Wfc  = (const float*)d_in[24];
    const float* bfc  = (const float*)d_in[25];
    float* out = (float*)d_out;

    float* S = nullptr;
    cudaGetSymbolAddress((void**)&S, g_scratch);

    cudaFuncSetAttribute(gemm_mma, cudaFuncAttributeMaxDynamicSharedMemorySize, MMA_SMEM);
    cudaFuncSetAttribute(gru_kernel, cudaFuncAttributeMaxDynamicSharedMemorySize, GRU_SMEM);

    // --- encoder layer 0: TF32x3 mma.sync, split-K=16, deterministic reduce ---
    gemm_mma<<<dim3(8, 2, GSPLITS), 256, MMA_SMEM>>>(x, W0, nullptr, S + S_WS,
                                                     K0, N0, GKC / 32, GKC,
                                                     (size_t)BATCH * N0);
    reduce_bias_kernel<<<1024, 256>>>(S + S_WS, b0, S + S_H0);
    bn_stats_kernel<<<4, 256>>>(S + S_H0, g0, be0, S + S_SCALE, S + S_SHIFT, 1024);
    bn_apply_kernel<<<1024, 256>>>(S + S_H0, S + S_SCALE, S + S_SHIFT, 1023);

    // --- encoder layer 1: 1024 -> 512 ---
    gemm_kernel<<<dim3(8, 4), 256>>>(S + S_H0, W1, b1, S + S_H1, 256, 512, 1024, 0);
    bn_stats_kernel<<<2, 256>>>(S + S_H1, g1, be1, S + S_SCALE, S + S_SHIFT, 512);
    bn_apply_kernel<<<512, 256>>>(S + S_H1, S + S_SCALE, S + S_SHIFT, 511);

    // --- encoder layer 2: 512 -> 256 ---
    gemm_kernel<<<dim3(4, 4), 256>>>(S + S_H1, W2, b2, S + S_H2B, 256, 256, 512, 0);
    bn_stats_kernel<<<1, 256>>>(S + S_H2B, g2, be2, S + S_SCALE, S + S_SHIFT, 256);
    bn_apply_kernel<<<256, 256>>>(S + S_H2B, S + S_SCALE, S + S_SHIFT, 255);

    // --- out layer (relu), mu, logvar ---
    gemm_kernel<<<dim3(2, 4), 256>>>(S + S_H2B, Wout, bout, S + S_HENC, 256, 128, 256, 1);
    gemm_kernel<<<dim3(2, 4), 256>>>(S + S_HENC, Wmu, bmu, S + S_MU, 256, 128, 128, 0);
    gemm_kernel<<<dim3(2, 4), 256>>>(S + S_HENC, Wlv, blv, S + S_LV, 256, 128, 128, 0);

    // --- reparameterize ---
    reparam_kernel<<<128, 256>>>(S + S_MU, S + S_LV, eps, S + S_Z, out);

    // --- GRU input projection ---
    gemm_kernel<<<dim3(6, 4), 256>>>(S + S_Z, Wih, bih, S + S_XP, 256, 384, 128, 0);

    // --- GRU recurrence ---
    gru_kernel<<<128, 384, GRU_SMEM>>>(S + S_XP, Whh, bhh, S + S_H2ALL);

    // --- logits via TF32x3 mma.sync (bias fused, direct write) ---
    gemm_mma<<<dim3(4, 256, 1), 256, MMA_SMEM>>>(S + S_H2ALL, Wfc, bfc, S + S_LOGITS,
                                                 GH, VOCAB, 4, 128, 0);
    argmax_onehot_kernel<<<4096, 256>>>(S + S_LOGITS, out);
}

// round 9
// speedup vs baseline: 2.3427x; 1.2908x over previous
#include <cuda_runtime.h>
#include <math.h>
#include <stdint.h>

typedef unsigned long long ull;

#define BATCH 256
#define SEQ   128
#define VOCAB 512
#define GH    128
#define K0    65536
#define N0    1024
#define GSPLITS 16
#define GKC   (K0/GSPLITS)   /* 4096 */

#define OFF_MU (BATCH*SEQ*VOCAB)
#define OFF_LV (OFF_MU + BATCH*GH)

// ---- scratch layout (single static __device__ array) ----
#define S_WS     0u                        /* 16 x 256 x 1024 split-K partials */
#define S_H0     (S_WS + 4194304u)         /* 256x1024 */
#define S_H1     (S_H0 + 262144u)          /* 256x512  */
#define S_H2B    (S_H1 + 131072u)          /* 256x256  */
#define S_HENC   (S_H2B + 65536u)          /* 256x128  */
#define S_MU     (S_HENC + 32768u)
#define S_LV     (S_MU + 32768u)
#define S_Z      (S_LV + 32768u)
#define S_XP     (S_Z + 32768u)            /* 256x384  */
#define S_H2ALL  (S_XP + 98304u)           /* 32768x128 */
#define S_AMP    (S_H2ALL + 4194304u)      /* 32768x4 float2 = 262144 floats */
#define S_SCALE  (S_AMP + 262144u)
#define S_SHIFT  (S_SCALE + 1024u)
#define S_TOTAL  (S_SHIFT + 1024u)

__device__ float g_scratch[S_TOTAL];

// ============================================================================
// fp16 split helpers
// ============================================================================
// pack two fp32 -> f16x2 (lo half = first arg, hi half = second arg)
__device__ __forceinline__ uint32_t packh2(float lo, float hi) {
    uint32_t r; asm("cvt.rn.f16x2.f32 %0, %1, %2;" : "=r"(r) : "f"(hi), "f"(lo)); return r;
}

// Veltkamp split: hi has 11 significand bits (== tf32), lo scaled by 2^11 so
// it stays in fp16 normal range even for 0.02-scale weights.
// MUST use non-contractable intrinsics (FMA fusion would break the split).
__device__ __forceinline__ void split11(float v, float& hi, float& lo) {
    float c = __fmul_rn(v, 8193.0f);
    hi = __fsub_rn(c, __fsub_rn(c, v));
    lo = __fmul_rn(__fsub_rn(v, hi), 2048.0f);
}

#define MMA_F16(acc, af, bf) asm volatile( \
    "mma.sync.aligned.m16n8k16.row.col.f32.f16.f16.f32 " \
    "{%0,%1,%2,%3}, {%4,%5,%6,%7}, {%8,%9}, {%0,%1,%2,%3};" \
    : "+f"((acc)[0]), "+f"((acc)[1]), "+f"((acc)[2]), "+f"((acc)[3]) \
    : "r"((af)[0]), "r"((af)[1]), "r"((af)[2]), "r"((af)[3]), \
      "r"((bf)[0]), "r"((bf)[1]))

// smem plane: 128 rows x 16 u32 (f16x2 pairs) padded to stride 20 -> conflict-free
#define PSTRIDE 20
#define PLANE   (128 * PSTRIDE)            /* 2560 u32 */
#define BUFU32  (4 * PLANE)                /* 10240 u32 per buffer */
#define MMA_SMEM (2 * BUFU32 * 4)          /* 81920 bytes */

// ============================================================================
// FP16-split (tf32x3-equivalent accuracy) tensor GEMM via mma.sync m16n8k16:
//   tile 128x128, BK=32, 8 warps (2m x 4n), warp tile 64x32.
//   amax == null: write split-K partials to C + blockIdx.z*splitStride
//   amax != null: add bias, per-row argmax over this CTA's 128 cols ->
//                 amax[row*4 + blockIdx.x] = (maxval, idx_as_float)
// ============================================================================
__global__ __launch_bounds__(256, 1) void gemm_mma(const float* __restrict__ A,
        const float* __restrict__ B, const float* __restrict__ bias,
        float* __restrict__ C, int ldA, int ldc, int nchunks, int kc,
        size_t splitStride, float2* __restrict__ amax) {
    extern __shared__ float smf[];
    uint32_t* smu = (uint32_t*)smf;
    const int tid  = threadIdx.x;
    const int lane = tid & 31;
    const int g    = lane >> 2;       // 0..7
    const int t    = lane & 3;        // 0..3
    const int warp = tid >> 5;
    const int m0w  = (warp >> 2) * 64;   // 0 or 64
    const int n0w  = (warp & 3) * 32;    // 0,32,64,96
    const int n0   = blockIdx.x * 128;
    const int m0   = blockIdx.y * 128;
    const int kbase = blockIdx.z * kc;

    const int rb = tid >> 3;          // 0..31
    const int q  = tid & 7;           // 0..7

    float accH[4][4][4], accL[4][4][4];
    #pragma unroll
    for (int mt = 0; mt < 4; mt++)
        #pragma unroll
        for (int nt = 0; nt < 4; nt++)
            #pragma unroll
            for (int i = 0; i < 4; i++) { accH[mt][nt][i] = 0.f; accL[mt][nt][i] = 0.f; }

    float4 stA[4], stB[4];

    // prologue: stage + convert chunk 0
    #pragma unroll
    for (int j = 0; j < 4; j++) {
        stA[j] = *(const float4*)&A[(size_t)(m0 + rb + 32*j) * ldA + kbase + q*4];
        stB[j] = *(const float4*)&B[(size_t)(n0 + rb + 32*j) * ldA + kbase + q*4];
    }
    {
        uint32_t* ahi = smu;           uint32_t* alo = smu + PLANE;
        uint32_t* bhi = smu + 2*PLANE; uint32_t* blo = smu + 3*PLANE;
        #pragma unroll
        for (int j = 0; j < 4; j++) {
            int off = (rb + 32*j) * PSTRIDE + 2*q;
            float4 v = stA[j];
            float hx,lx,hy,ly,hz,lz,hw,lw;
            split11(v.x,hx,lx); split11(v.y,hy,ly); split11(v.z,hz,lz); split11(v.w,hw,lw);
            *(uint2*)&ahi[off] = make_uint2(packh2(hx,hy), packh2(hz,hw));
            *(uint2*)&alo[off] = make_uint2(packh2(lx,ly), packh2(lz,lw));
            v = stB[j];
            split11(v.x,hx,lx); split11(v.y,hy,ly); split11(v.z,hz,lz); split11(v.w,hw,lw);
            *(uint2*)&bhi[off] = make_uint2(packh2(hx,hy), packh2(hz,hw));
            *(uint2*)&blo[off] = make_uint2(packh2(lx,ly), packh2(lz,lw));
        }
    }
    __syncthreads();

    for (int c = 0; c < nchunks; c++) {
        if (c + 1 < nchunks) {
            int kp = kbase + (c + 1) * 32;
            #pragma unroll
            for (int j = 0; j < 4; j++) {
                stA[j] = *(const float4*)&A[(size_t)(m0 + rb + 32*j) * ldA + kp + q*4];
                stB[j] = *(const float4*)&B[(size_t)(n0 + rb + 32*j) * ldA + kp + q*4];
            }
        }

        const uint32_t* base = smu + (c & 1) * BUFU32;
        const uint32_t* pAhi = base;
        const uint32_t* pAlo = base + PLANE;
        const uint32_t* pBhi = base + 2*PLANE;
        const uint32_t* pBlo = base + 3*PLANE;

        #pragma unroll
        for (int ks = 0; ks < 2; ks++) {
            const int kk = ks * 8;
            uint32_t aH[4][4], aL[4][4], bH[4][2], bL[4][2];
            #pragma unroll
            for (int mt = 0; mt < 4; mt++) {
                int ro = (m0w + mt*16 + g) * PSTRIDE + kk + t;
                aH[mt][0] = pAhi[ro];
                aH[mt][1] = pAhi[ro + 8*PSTRIDE];
                aH[mt][2] = pAhi[ro + 4];
                aH[mt][3] = pAhi[ro + 8*PSTRIDE + 4];
                aL[mt][0] = pAlo[ro];
                aL[mt][1] = pAlo[ro + 8*PSTRIDE];
                aL[mt][2] = pAlo[ro + 4];
                aL[mt][3] = pAlo[ro + 8*PSTRIDE + 4];
            }
            #pragma unroll
            for (int nt = 0; nt < 4; nt++) {
                int rn = (n0w + nt*8 + g) * PSTRIDE + kk + t;
                bH[nt][0] = pBhi[rn];
                bH[nt][1] = pBhi[rn + 4];
                bL[nt][0] = pBlo[rn];
                bL[nt][1] = pBlo[rn + 4];
            }
            #pragma unroll
            for (int mt = 0; mt < 4; mt++)
                #pragma unroll
                for (int nt = 0; nt < 4; nt++) {
                    MMA_F16(accH[mt][nt], aH[mt], bH[nt]);
                    MMA_F16(accL[mt][nt], aH[mt], bL[nt]);
                    MMA_F16(accL[mt][nt], aL[mt], bH[nt]);
                }
        }

        if (c + 1 < nchunks) {
            uint32_t* bb = smu + ((c + 1) & 1) * BUFU32;
            uint32_t* ahi = bb;           uint32_t* alo = bb + PLANE;
            uint32_t* bhi = bb + 2*PLANE; uint32_t* blo = bb + 3*PLANE;
            #pragma unroll
            for (int j = 0; j < 4; j++) {
                int off = (rb + 32*j) * PSTRIDE + 2*q;
                float4 v = stA[j];
                float hx,lx,hy,ly,hz,lz,hw,lw;
                split11(v.x,hx,lx); split11(v.y,hy,ly); split11(v.z,hz,lz); split11(v.w,hw,lw);
                *(uint2*)&ahi[off] = make_uint2(packh2(hx,hy), packh2(hz,hw));
                *(uint2*)&alo[off] = make_uint2(packh2(lx,ly), packh2(lz,lw));
                v = stB[j];
                split11(v.x,hx,lx); split11(v.y,hy,ly); split11(v.z,hz,lz); split11(v.w,hw,lw);
                *(uint2*)&bhi[off] = make_uint2(packh2(hx,hy), packh2(hz,hw));
                *(uint2*)&blo[off] = make_uint2(packh2(lx,ly), packh2(lz,lw));
            }
        }
        __syncthreads();
    }

    const float inv2048 = 1.0f / 2048.0f;

    if (amax == nullptr) {
        // split-K partial write
        float* Cp = C + (size_t)blockIdx.z * splitStride;
        #pragma unroll
        for (int mt = 0; mt < 4; mt++) {
            #pragma unroll
            for (int nt = 0; nt < 4; nt++) {
                int row = m0 + m0w + mt*16 + g;
                int col = n0 + n0w + nt*8 + 2*t;
                float2 v0 = make_float2(accH[mt][nt][0] + accL[mt][nt][0]*inv2048,
                                        accH[mt][nt][1] + accL[mt][nt][1]*inv2048);
                float2 v1 = make_float2(accH[mt][nt][2] + accL[mt][nt][2]*inv2048,
                                        accH[mt][nt][3] + accL[mt][nt][3]*inv2048);
                *(float2*)&Cp[(size_t)row * ldc + col] = v0;
                *(float2*)&Cp[(size_t)(row + 8) * ldc + col] = v1;
            }
        }
    } else {
        // bias + per-row argmax over this CTA's 128 cols
        float2* sred = (float2*)smf;   // [128 rows][4 warp_n]
        const int warp_n = warp & 3;
        #pragma unroll
        for (int half = 0; half < 2; half++) {
            #pragma unroll
            for (int mt = 0; mt < 4; mt++) {
                int rloc = m0w + mt*16 + g + half*8;
                float best = -1e30f; int bidx = 0;
                #pragma unroll
                for (int nt = 0; nt < 4; nt++) {
                    #pragma unroll
                    for (int e = 0; e < 2; e++) {
                        int col = n0 + n0w + nt*8 + 2*t + e;
                        float v = accH[mt][nt][half*2 + e] + accL[mt][nt][half*2 + e]*inv2048
                                  + bias[col];
                        if (v > best) { best = v; bidx = col; }
                    }
                }
                #pragma unroll
                for (int o = 1; o < 4; o <<= 1) {
                    float ov = __shfl_xor_sync(0xffffffffu, best, o);
                    int   oi = __shfl_xor_sync(0xffffffffu, bidx, o);
                    if (ov > best || (ov == best && oi < bidx)) { best = ov; bidx = oi; }
                }
                if (t == 0) sred[rloc * 4 + warp_n] = make_float2(best, __int_as_float(bidx));
            }
        }
        __syncthreads();
        if (tid < 128) {
            float best = -1e30f; int bidx = 0x7fffffff;
            #pragma unroll
            for (int wn = 0; wn < 4; wn++) {
                float2 e = sred[tid * 4 + wn];
                int ei = __float_as_int(e.y);
                if (e.x > best || (e.x == best && ei < bidx)) { best = e.x; bidx = ei; }
            }
            amax[(size_t)(m0 + tid) * 4 + blockIdx.x] = make_float2(best, __int_as_float(bidx));
        }
    }
}

// deterministic split-K reduce + bias (GEMM0)
__global__ __launch_bounds__(256) void reduce_bias_kernel(const float* __restrict__ ws,
                                                          const float* __restrict__ bias,
                                                          float* __restrict__ out) {
    int i = blockIdx.x * 256 + threadIdx.x;   // < 262144
    float s = 0.0f;
    #pragma unroll
    for (int sp = 0; sp < GSPLITS; sp++) s += ws[(size_t)sp * (BATCH * N0) + i];
    out[i] = s + bias[i & (N0 - 1)];
}

// ============================================================================
// BatchNorm (2-pass) + LeakyReLU
// ============================================================================
__global__ void bn_stats_kernel(const float* __restrict__ h, const float* __restrict__ g,
                                const float* __restrict__ be, float* __restrict__ scale,
                                float* __restrict__ shift, int N) {
    int f = blockIdx.x * 256 + threadIdx.x;
    if (f >= N) return;
    float s = 0.f, ss = 0.f;
    #pragma unroll 4
    for (int b = 0; b < BATCH; b++) {
        float v = h[(size_t)b * N + f];
        s += v; ss += v * v;
    }
    float mean = s * (1.0f / BATCH);
    float var = ss * (1.0f / BATCH) - mean * mean;
    float sc = rsqrtf(var + 1e-5f) * g[f];
    scale[f] = sc;
    shift[f] = be[f] - mean * sc;
}

__global__ void bn_apply_kernel(float* __restrict__ h, const float* __restrict__ scale,
                                const float* __restrict__ shift, int nmask) {
    int i = blockIdx.x * 256 + threadIdx.x;
    int f = i & nmask;
    float o = h[i] * scale[f] + shift[f];
    h[i] = o > 0.f ? o : 0.01f * o;
}

// ============================================================================
// Generic fp32x2 GEMM (small layers): C = act(A[M,K] @ W[N,K]^T + bias)
// ============================================================================
__device__ __forceinline__ void fma2(ull &d, ull a, ull b) {
    asm("fma.rn.f32x2 %0, %1, %2, %0;" : "+l"(d) : "l"(a), "l"(b));
}
__device__ __forceinline__ ull pk2(float x, float y) {
    ull d; asm("mov.b64 %0, {%1, %2};" : "=l"(d) : "f"(x), "f"(y)); return d;
}
__device__ __forceinline__ float2 unpk2(ull d) {
    float2 r; asm("mov.b64 {%0, %1}, %2;" : "=f"(r.x), "=f"(r.y) : "l"(d)); return r;
}

__global__ __launch_bounds__(256) void gemm_kernel(const float* __restrict__ A,
        const float* __restrict__ W, const float* __restrict__ bias,
        float* __restrict__ C, int M, int N, int K, int act) {
    __shared__ float As[16][68];
    __shared__ float Bs[16][68];
    const int tid = threadIdx.x;
    const int n0 = blockIdx.x * 64;
    const int m0 = blockIdx.y * 64;
    const int trow = tid >> 4;
    const int tcol = tid & 15;
    const int lm = tid >> 2;
    const int lk = (tid & 3) * 4;

    ull acc[4][2];
    #pragma unroll
    for (int r = 0; r < 4; r++) { acc[r][0] = 0ull; acc[r][1] = 0ull; }

    for (int kk = 0; kk < K; kk += 16) {
        float4 va = *(const float4*)&A[(size_t)(m0 + lm) * K + kk + lk];
        float4 vb = *(const float4*)&W[(size_t)(n0 + lm) * K + kk + lk];
        As[lk+0][lm] = va.x; As[lk+1][lm] = va.y; As[lk+2][lm] = va.z; As[lk+3][lm] = va.w;
        Bs[lk+0][lm] = vb.x; Bs[lk+1][lm] = vb.y; Bs[lk+2][lm] = vb.z; Bs[lk+3][lm] = vb.w;
        __syncthreads();
        #pragma unroll
        for (int k = 0; k < 16; k++) {
            float4 a = *(const float4*)&As[k][trow * 4];
            const ull* bp = (const ull*)&Bs[k][tcol * 4];
            ull b0 = bp[0], b1 = bp[1];
            ull a0 = pk2(a.x, a.x), a1 = pk2(a.y, a.y);
            ull a2 = pk2(a.z, a.z), a3 = pk2(a.w, a.w);
            fma2(acc[0][0], a0, b0); fma2(acc[0][1], a0, b1);
            fma2(acc[1][0], a1, b0); fma2(acc[1][1], a1, b1);
            fma2(acc[2][0], a2, b0); fma2(acc[2][1], a2, b1);
            fma2(acc[3][0], a3, b0); fma2(acc[3][1], a3, b1);
        }
        __syncthreads();
    }

    #pragma unroll
    for (int r = 0; r < 4; r++) {
        int m = m0 + trow * 4 + r;
        int n = n0 + tcol * 4;
        float2 v0 = unpk2(acc[r][0]);
        float2 v1 = unpk2(acc[r][1]);
        float o0 = v0.x + bias[n+0];
        float o1 = v0.y + bias[n+1];
        float o2 = v1.x + bias[n+2];
        float o3 = v1.y + bias[n+3];
        if (act == 1) {
            o0 = fmaxf(o0, 0.f); o1 = fmaxf(o1, 0.f);
            o2 = fmaxf(o2, 0.f); o3 = fmaxf(o3, 0.f);
        }
        *(float4*)&C[(size_t)m * N + n] = make_float4(o0, o1, o2, o3);
    }
}

// ============================================================================
// reparameterize + emit mu/logvar to output tail
// ============================================================================
__global__ void reparam_kernel(const float* __restrict__ mu, const float* __restrict__ lv,
                               const float* __restrict__ eps, float* __restrict__ z,
                               float* __restrict__ out) {
    int i = blockIdx.x * 256 + threadIdx.x;
    float m = mu[i], l = lv[i];
    z[i] = m + eps[i] * expf(0.5f * l);
    out[OFF_MU + i] = m;
    out[OFF_LV + i] = l;
}

// ============================================================================
// GRU recurrence (persistent, 128 CTAs x 384 thr, 2 rows/CTA)
// ============================================================================
#define GRU_SMEM 205312
__global__ __launch_bounds__(384, 1) void gru_kernel(const float* __restrict__ xp,
        const float* __restrict__ Whh, const float* __restrict__ bhh,
        float* __restrict__ h2all) {
    extern __shared__ float sm[];
    float4* whh4 = (float4*)sm;
    float* h_s   = sm + 49152;
    float* hp_s  = sm + 49152 + 256;
    float* xp_s  = sm + 49152 + 1024;
    float* bhh_s = sm + 49152 + 1792;
    const int j = threadIdx.x;
    const int row0 = blockIdx.x * 2;

    #pragma unroll 4
    for (int kq = 0; kq < 32; kq++)
        whh4[kq * 384 + j] = *(const float4*)&Whh[(size_t)j * GH + kq * 4];
    bhh_s[j] = bhh[j];
    xp_s[j]       = xp[(size_t)row0 * 384 + j];
    xp_s[384 + j] = xp[(size_t)(row0 + 1) * 384 + j];
    if (j < 256) h_s[j] = 0.0f;
    __syncthreads();

    for (int t = 0; t < SEQ; t++) {
        float acc0 = 0.f, acc1 = 0.f;
        const float4* wp = whh4 + j;
        #pragma unroll 8
        for (int kq = 0; kq < 32; kq++) {
            float4 w  = wp[kq * 384];
            float4 ha = *(const float4*)&h_s[kq * 4];
            float4 hb = *(const float4*)&h_s[128 + kq * 4];
            acc0 += w.x*ha.x + w.y*ha.y + w.z*ha.z + w.w*ha.w;
            acc1 += w.x*hb.x + w.y*hb.y + w.z*hb.z + w.w*hb.w;
        }
        hp_s[j]       = acc0 + bhh_s[j];
        hp_s[384 + j] = acc1 + bhh_s[j];
        __syncthreads();
        if (j < 256) {
            int r = j >> 7, u = j & 127;
            const float* hp = hp_s + r * 384;
            const float* xq = xp_s + r * 384;
            float rg = 1.0f / (1.0f + expf(-(xq[u]       + hp[u])));
            float zg = 1.0f / (1.0f + expf(-(xq[128 + u] + hp[128 + u])));
            float nn = tanhf(xq[256 + u] + rg * hp[256 + u]);
            float hold = h_s[r * 128 + u];
            float hnew = (1.0f - zg) * nn + zg * hold;
            h_s[r * 128 + u] = hnew;
            h2all[((size_t)t * BATCH + row0 + r) * GH + u] = hnew;
        }
        __syncthreads();
    }
}

// ============================================================================
// final argmax reduce over 4 partials + one-hot write
// ============================================================================
__global__ __launch_bounds__(256) void argmax_final(const float2* __restrict__ amp,
                                                    float* __restrict__ out) {
    int row  = blockIdx.x * 8 + (threadIdx.x >> 5);   // < 32768
    int lane = threadIdx.x & 31;
    float best = -1e30f; int bi = 0x7fffffff;
    if (lane < 4) {
        float2 e = amp[(size_t)row * 4 + lane];
        best = e.x; bi = __float_as_int(e.y);
    }
    #pragma unroll
    for (int o = 1; o < 4; o <<= 1) {
        float ov = __shfl_xor_sync(0xffffffffu, best, o);
        int   oi = __shfl_xor_sync(0xffffffffu, bi, o);
        if (ov > best || (ov == best && oi < bi)) { best = ov; bi = oi; }
    }
    bi = __shfl_sync(0xffffffffu, bi, 0);
    int t = row >> 8, b = row & 255;
    float* op = out + (size_t)b * (SEQ * VOCAB) + (size_t)t * VOCAB;
    #pragma unroll
    for (int q = 0; q < 4; q++) {
        int c = lane * 16 + q * 4;
        *(float4*)&op[c] = make_float4(c == bi ? 1.f : 0.f, c + 1 == bi ? 1.f : 0.f,
                                       c + 2 == bi ? 1.f : 0.f, c + 3 == bi ? 1.f : 0.f);
    }
}

// ============================================================================
// launcher
// ============================================================================
extern "C" void kernel_launch(void* const* d_in, const int* in_sizes, int n_in,
                              void* d_out, int out_size) {
    (void)in_sizes; (void)n_in; (void)out_size;
    const float* x    = (const float*)d_in[0];
    const float* eps  = (const float*)d_in[1];
    const float* W0   = (const float*)d_in[2];
    const float* b0   = (const float*)d_in[3];
    const float* g0   = (const float*)d_in[4];
    const float* be0  = (const float*)d_in[5];
    const float* W1   = (const float*)d_in[6];
    const float* b1   = (const float*)d_in[7];
    const float* g1   = (const float*)d_in[8];
    const float* be1  = (const float*)d_in[9];
    const float* W2   = (const float*)d_in[10];
    const float* b2   = (const float*)d_in[11];
    const float* g2   = (const float*)d_in[12];
    const float* be2  = (const float*)d_in[13];
    const float* Wout = (const float*)d_in[14];
    const float* bout = (const float*)d_in[15];
    const float* Wmu  = (const float*)d_in[16];
    const float* bmu  = (const float*)d_in[17];
    const float* Wlv  = (const float*)d_in[18];
    const float* blv  = (const float*)d_in[19];
    const float* Wih  = (const float*)d_in[20];
    const float* bih  = (const float*)d_in[21];
    const float* Whh  = (const float*)d_in[22];
    const float* bhh  = (const float*)d_in[23];
    const float* Wfc  = (const float*)d_in[24];
    const float* bfc  = (const float*)d_in[25];
    float* out = (float*)d_out;

    float* S = nullptr;
    cudaGetSymbolAddress((void**)&S, g_scratch);

    cudaFuncSetAttribute(gemm_mma, cudaFuncAttributeMaxDynamicSharedMemorySize, MMA_SMEM);
    cudaFuncSetAttribute(gru_kernel, cudaFuncAttributeMaxDynamicSharedMemorySize, GRU_SMEM);

    // --- encoder layer 0: fp16-split (tf32x3-accuracy) mma, split-K=16 ---
    gemm_mma<<<dim3(8, 2, GSPLITS), 256, MMA_SMEM>>>(x, W0, nullptr, S + S_WS,
                                                     K0, N0, GKC / 32, GKC,
                                                     (size_t)BATCH * N0, nullptr);
    reduce_bias_kernel<<<1024, 256>>>(S + S_WS, b0, S + S_H0);
    bn_stats_kernel<<<4, 256>>>(S + S_H0, g0, be0, S + S_SCALE, S + S_SHIFT, 1024);
    bn_apply_kernel<<<1024, 256>>>(S + S_H0, S + S_SCALE, S + S_SHIFT, 1023);

    // --- encoder layer 1: 1024 -> 512 ---
    gemm_kernel<<<dim3(8, 4), 256>>>(S + S_H0, W1, b1, S + S_H1, 256, 512, 1024, 0);
    bn_stats_kernel<<<2, 256>>>(S + S_H1, g1, be1, S + S_SCALE, S + S_SHIFT, 512);
    bn_apply_kernel<<<512, 256>>>(S + S_H1, S + S_SCALE, S + S_SHIFT, 511);

    // --- encoder layer 2: 512 -> 256 ---
    gemm_kernel<<<dim3(4, 4), 256>>>(S + S_H1, W2, b2, S + S_H2B, 256, 256, 512, 0);
    bn_stats_kernel<<<1, 256>>>(S + S_H2B, g2, be2, S + S_SCALE, S + S_SHIFT, 256);
    bn_apply_kernel<<<256, 256>>>(S + S_H2B, S + S_SCALE, S + S_SHIFT, 255);

    // --- out layer (relu), mu, logvar ---
    gemm_kernel<<<dim3(2, 4), 256>>>(S + S_H2B, Wout, bout, S + S_HENC, 256, 128, 256, 1);
    gemm_kernel<<<dim3(2, 4), 256>>>(S + S_HENC, Wmu, bmu, S + S_MU, 256, 128, 128, 0);
    gemm_kernel<<<dim3(2, 4), 256>>>(S + S_HENC, Wlv, blv, S + S_LV, 256, 128, 128, 0);

    // --- reparameterize ---
    reparam_kernel<<<128, 256>>>(S + S_MU, S + S_LV, eps, S + S_Z, out);

    // --- GRU input projection ---
    gemm_kernel<<<dim3(6, 4), 256>>>(S + S_Z, Wih, bih, S + S_XP, 256, 384, 128, 0);

    // --- GRU recurrence ---
    gru_kernel<<<128, 384, GRU_SMEM>>>(S + S_XP, Whh, bhh, S + S_H2ALL);

    // --- logits GEMM with fused bias+argmax partials (no logits round-trip) ---
    gemm_mma<<<dim3(4, 256, 1), 256, MMA_SMEM>>>(S + S_H2ALL, Wfc, bfc, nullptr,
                                                 GH, 0, 4, 128, 0,
                                                 (float2*)(S + S_AMP));
    argmax_final<<<4096, 256>>>((const float2*)(S + S_AMP), out);
}

// round 10
// speedup vs baseline: 2.8527x; 1.2177x over previous
#include <cuda_runtime.h>
#include <math.h>
#include <stdint.h>

typedef unsigned long long ull;

#define BATCH 256
#define SEQ   128
#define VOCAB 512
#define GH    128
#define K0    65536
#define N0    1024
#define GSPLITS 9
#define TCHUNKS0 2048          /* K0/32 */

#define OFF_MU (BATCH*SEQ*VOCAB)
#define OFF_LV (OFF_MU + BATCH*GH)

// ---- scratch layout (single static __device__ array) ----
#define S_WS     0u                        /* 9 x 256 x 1024 split-K partials */
#define S_H0     (S_WS + 2359296u)         /* 256x1024 (raw, pre-BN) */
#define S_H1     (S_H0 + 262144u)          /* 256x512  (raw) */
#define S_H2B    (S_H1 + 131072u)          /* 256x256  (raw) */
#define S_HENC   (S_H2B + 65536u)          /* 256x128  */
#define S_MU     (S_HENC + 32768u)
#define S_LV     (S_MU + 32768u)
#define S_Z      (S_LV + 32768u)
#define S_XP     (S_Z + 32768u)            /* 256x384  */
#define S_H2ALL  (S_XP + 98304u)           /* 32768x128 */
#define S_AMP    (S_H2ALL + 4194304u)      /* 32768x4 float2 */
#define S_SCALE  (S_AMP + 262144u)
#define S_SHIFT  (S_SCALE + 1024u)
#define S_TOTAL  (S_SHIFT + 1024u)

__device__ float g_scratch[S_TOTAL];

// ============================================================================
// fp16 split helpers
// ============================================================================
__device__ __forceinline__ uint32_t packh2(float lo, float hi) {
    uint32_t r; asm("cvt.rn.f16x2.f32 %0, %1, %2;" : "=r"(r) : "f"(hi), "f"(lo)); return r;
}

// truncation split: hi = top 11 significand bits (exact in fp16),
// lo = (v - hi) * 2048 (exact fp32 sub; fp16 keeps top 11 of remainder).
// AND goes to ALU pipe (relieves FMA pipe). Total captured ~22-24 bits.
__device__ __forceinline__ void split11(float v, float& hi, float& lo) {
    hi = __uint_as_float(__float_as_uint(v) & 0xFFFFE000u);
    lo = __fmul_rn(__fsub_rn(v, hi), 2048.0f);
}

#define MMA_F16(acc, af, bf) asm volatile( \
    "mma.sync.aligned.m16n8k16.row.col.f32.f16.f16.f32 " \
    "{%0,%1,%2,%3}, {%4,%5,%6,%7}, {%8,%9}, {%0,%1,%2,%3};" \
    : "+f"((acc)[0]), "+f"((acc)[1]), "+f"((acc)[2]), "+f"((acc)[3]) \
    : "r"((af)[0]), "r"((af)[1]), "r"((af)[2]), "r"((af)[3]), \
      "r"((bf)[0]), "r"((bf)[1]))

// smem plane: 128 rows x 16 u32 (f16x2 pairs) padded to stride 20 -> conflict-free
#define PSTRIDE 20
#define PLANE   (128 * PSTRIDE)            /* 2560 u32 */
#define BUFU32  (4 * PLANE)                /* 10240 u32 per buffer */
#define MMA_SMEM (2 * BUFU32 * 4)          /* 81920 bytes */

// ============================================================================
// FP16-split tensor GEMM via mma.sync m16n8k16:
//   tile 128x128, BK=32, 8 warps (2m x 4n), warp tile 64x32.
//   K split into nsplit variable ranges over tchunks 32-wide chunks.
//   amax == null: write split-K partials to C + blockIdx.z*splitStride
//   amax != null: add bias, per-row argmax over this CTA's 128 cols
// ============================================================================
__global__ __launch_bounds__(256, 1) void gemm_mma(const float* __restrict__ A,
        const float* __restrict__ B, const float* __restrict__ bias,
        float* __restrict__ C, int ldA, int ldc, int tchunks, int nsplit,
        size_t splitStride, float2* __restrict__ amax) {
    extern __shared__ float smf[];
    uint32_t* smu = (uint32_t*)smf;
    const int tid  = threadIdx.x;
    const int lane = tid & 31;
    const int g    = lane >> 2;       // 0..7
    const int t    = lane & 3;        // 0..3
    const int warp = tid >> 5;
    const int m0w  = (warp >> 2) * 64;   // 0 or 64
    const int n0w  = (warp & 3) * 32;    // 0,32,64,96
    const int n0   = blockIdx.x * 128;
    const int m0   = blockIdx.y * 128;

    const int cs = (int)(((long long)blockIdx.z * tchunks) / nsplit);
    const int ce = (int)(((long long)(blockIdx.z + 1) * tchunks) / nsplit);
    const int nchunks = ce - cs;
    const int kbase = cs * 32;

    const int rb = tid >> 3;          // 0..31
    const int q  = tid & 7;           // 0..7

    float accH[4][4][4], accL[4][4][4];
    #pragma unroll
    for (int mt = 0; mt < 4; mt++)
        #pragma unroll
        for (int nt = 0; nt < 4; nt++)
            #pragma unroll
            for (int i = 0; i < 4; i++) { accH[mt][nt][i] = 0.f; accL[mt][nt][i] = 0.f; }

    float4 stA[4], stB[4];

    // prologue: stage + convert chunk 0
    #pragma unroll
    for (int j = 0; j < 4; j++) {
        stA[j] = *(const float4*)&A[(size_t)(m0 + rb + 32*j) * ldA + kbase + q*4];
        stB[j] = *(const float4*)&B[(size_t)(n0 + rb + 32*j) * ldA + kbase + q*4];
    }
    {
        uint32_t* ahi = smu;           uint32_t* alo = smu + PLANE;
        uint32_t* bhi = smu + 2*PLANE; uint32_t* blo = smu + 3*PLANE;
        #pragma unroll
        for (int j = 0; j < 4; j++) {
            int off = (rb + 32*j) * PSTRIDE + 2*q;
            float4 v = stA[j];
            float hx,lx,hy,ly,hz,lz,hw,lw;
            split11(v.x,hx,lx); split11(v.y,hy,ly); split11(v.z,hz,lz); split11(v.w,hw,lw);
            *(uint2*)&ahi[off] = make_uint2(packh2(hx,hy), packh2(hz,hw));
            *(uint2*)&alo[off] = make_uint2(packh2(lx,ly), packh2(lz,lw));
            v = stB[j];
            split11(v.x,hx,lx); split11(v.y,hy,ly); split11(v.z,hz,lz); split11(v.w,hw,lw);
            *(uint2*)&bhi[off] = make_uint2(packh2(hx,hy), packh2(hz,hw));
            *(uint2*)&blo[off] = make_uint2(packh2(lx,ly), packh2(lz,lw));
        }
    }
    __syncthreads();

    for (int c = 0; c < nchunks; c++) {
        if (c + 1 < nchunks) {
            int kp = kbase + (c + 1) * 32;
            #pragma unroll
            for (int j = 0; j < 4; j++) {
                stA[j] = *(const float4*)&A[(size_t)(m0 + rb + 32*j) * ldA + kp + q*4];
                stB[j] = *(const float4*)&B[(size_t)(n0 + rb + 32*j) * ldA + kp + q*4];
            }
        }

        const uint32_t* base = smu + (c & 1) * BUFU32;
        const uint32_t* pAhi = base;
        const uint32_t* pAlo = base + PLANE;
        const uint32_t* pBhi = base + 2*PLANE;
        const uint32_t* pBlo = base + 3*PLANE;

        #pragma unroll
        for (int ks = 0; ks < 2; ks++) {
            const int kk = ks * 8;
            uint32_t aH[4][4], aL[4][4], bH[4][2], bL[4][2];
            #pragma unroll
            for (int mt = 0; mt < 4; mt++) {
                int ro = (m0w + mt*16 + g) * PSTRIDE + kk + t;
                aH[mt][0] = pAhi[ro];
                aH[mt][1] = pAhi[ro + 8*PSTRIDE];
                aH[mt][2] = pAhi[ro + 4];
                aH[mt][3] = pAhi[ro + 8*PSTRIDE + 4];
                aL[mt][0] = pAlo[ro];
                aL[mt][1] = pAlo[ro + 8*PSTRIDE];
                aL[mt][2] = pAlo[ro + 4];
                aL[mt][3] = pAlo[ro + 8*PSTRIDE + 4];
            }
            #pragma unroll
            for (int nt = 0; nt < 4; nt++) {
                int rn = (n0w + nt*8 + g) * PSTRIDE + kk + t;
                bH[nt][0] = pBhi[rn];
                bH[nt][1] = pBhi[rn + 4];
                bL[nt][0] = pBlo[rn];
                bL[nt][1] = pBlo[rn + 4];
            }
            #pragma unroll
            for (int mt = 0; mt < 4; mt++)
                #pragma unroll
                for (int nt = 0; nt < 4; nt++) {
                    MMA_F16(accH[mt][nt], aH[mt], bH[nt]);
                    MMA_F16(accL[mt][nt], aH[mt], bL[nt]);
                    MMA_F16(accL[mt][nt], aL[mt], bH[nt]);
                }
        }

        if (c + 1 < nchunks) {
            uint32_t* bb = smu + ((c + 1) & 1) * BUFU32;
            uint32_t* ahi = bb;           uint32_t* alo = bb + PLANE;
            uint32_t* bhi = bb + 2*PLANE; uint32_t* blo = bb + 3*PLANE;
            #pragma unroll
            for (int j = 0; j < 4; j++) {
                int off = (rb + 32*j) * PSTRIDE + 2*q;
                float4 v = stA[j];
                float hx,lx,hy,ly,hz,lz,hw,lw;
                split11(v.x,hx,lx); split11(v.y,hy,ly); split11(v.z,hz,lz); split11(v.w,hw,lw);
                *(uint2*)&ahi[off] = make_uint2(packh2(hx,hy), packh2(hz,hw));
                *(uint2*)&alo[off] = make_uint2(packh2(lx,ly), packh2(lz,lw));
                v = stB[j];
                split11(v.x,hx,lx); split11(v.y,hy,ly); split11(v.z,hz,lz); split11(v.w,hw,lw);
                *(uint2*)&bhi[off] = make_uint2(packh2(hx,hy), packh2(hz,hw));
                *(uint2*)&blo[off] = make_uint2(packh2(lx,ly), packh2(lz,lw));
            }
        }
        __syncthreads();
    }

    const float inv2048 = 1.0f / 2048.0f;

    if (amax == nullptr) {
        float* Cp = C + (size_t)blockIdx.z * splitStride;
        #pragma unroll
        for (int mt = 0; mt < 4; mt++) {
            #pragma unroll
            for (int nt = 0; nt < 4; nt++) {
                int row = m0 + m0w + mt*16 + g;
                int col = n0 + n0w + nt*8 + 2*t;
                float2 v0 = make_float2(accH[mt][nt][0] + accL[mt][nt][0]*inv2048,
                                        accH[mt][nt][1] + accL[mt][nt][1]*inv2048);
                float2 v1 = make_float2(accH[mt][nt][2] + accL[mt][nt][2]*inv2048,
                                        accH[mt][nt][3] + accL[mt][nt][3]*inv2048);
                *(float2*)&Cp[(size_t)row * ldc + col] = v0;
                *(float2*)&Cp[(size_t)(row + 8) * ldc + col] = v1;
            }
        }
    } else {
        // bias + per-row argmax over this CTA's 128 cols
        float2* sred = (float2*)smf;   // [128 rows][4 warp_n]
        const int warp_n = warp & 3;
        #pragma unroll
        for (int half = 0; half < 2; half++) {
            #pragma unroll
            for (int mt = 0; mt < 4; mt++) {
                int rloc = m0w + mt*16 + g + half*8;
                float best = -1e30f; int bidx = 0;
                #pragma unroll
                for (int nt = 0; nt < 4; nt++) {
                    #pragma unroll
                    for (int e = 0; e < 2; e++) {
                        int col = n0 + n0w + nt*8 + 2*t + e;
                        float v = accH[mt][nt][half*2 + e] + accL[mt][nt][half*2 + e]*inv2048
                                  + bias[col];
                        if (v > best) { best = v; bidx = col; }
                    }
                }
                #pragma unroll
                for (int o = 1; o < 4; o <<= 1) {
                    float ov = __shfl_xor_sync(0xffffffffu, best, o);
                    int   oi = __shfl_xor_sync(0xffffffffu, bidx, o);
                    if (ov > best || (ov == best && oi < bidx)) { best = ov; bidx = oi; }
                }
                if (t == 0) sred[rloc * 4 + warp_n] = make_float2(best, __int_as_float(bidx));
            }
        }
        __syncthreads();
        if (tid < 128) {
            float best = -1e30f; int bidx = 0x7fffffff;
            #pragma unroll
            for (int wn = 0; wn < 4; wn++) {
                float2 e = sred[tid * 4 + wn];
                int ei = __float_as_int(e.y);
                if (e.x > best || (e.x == best && ei < bidx)) { best = e.x; bidx = ei; }
            }
            amax[(size_t)(m0 + tid) * 4 + blockIdx.x] = make_float2(best, __int_as_float(bidx));
        }
    }
}

// deterministic split-K reduce + bias (GEMM0)
__global__ __launch_bounds__(256) void reduce_bias_kernel(const float* __restrict__ ws,
                                                          const float* __restrict__ bias,
                                                          float* __restrict__ out) {
    int i = blockIdx.x * 256 + threadIdx.x;   // < 262144
    float s = 0.0f;
    #pragma unroll
    for (int sp = 0; sp < GSPLITS; sp++) s += ws[(size_t)sp * (BATCH * N0) + i];
    out[i] = s + bias[i & (N0 - 1)];
}

// ============================================================================
// BatchNorm stats (scale/shift); apply is fused into the consumer GEMM
// ============================================================================
__global__ void bn_stats_kernel(const float* __restrict__ h, const float* __restrict__ g,
                                const float* __restrict__ be, float* __restrict__ scale,
                                float* __restrict__ shift, int N) {
    int f = blockIdx.x * 256 + threadIdx.x;
    if (f >= N) return;
    float s = 0.f, ss = 0.f;
    #pragma unroll 4
    for (int b = 0; b < BATCH; b++) {
        float v = h[(size_t)b * N + f];
        s += v; ss += v * v;
    }
    float mean = s * (1.0f / BATCH);
    float var = ss * (1.0f / BATCH) - mean * mean;
    float sc = rsqrtf(var + 1e-5f) * g[f];
    scale[f] = sc;
    shift[f] = be[f] - mean * sc;
}

// ============================================================================
// Generic fp32x2 GEMM (small layers): C = act(A'[M,K] @ W[N,K]^T + bias)
// where A' = lrelu(A*scA + shA) if scA != null (fused BatchNorm+LeakyReLU)
// ============================================================================
__device__ __forceinline__ void fma2(ull &d, ull a, ull b) {
    asm("fma.rn.f32x2 %0, %1, %2, %0;" : "+l"(d) : "l"(a), "l"(b));
}
__device__ __forceinline__ ull pk2(float x, float y) {
    ull d; asm("mov.b64 %0, {%1, %2};" : "=l"(d) : "f"(x), "f"(y)); return d;
}
__device__ __forceinline__ float2 unpk2(ull d) {
    float2 r; asm("mov.b64 {%0, %1}, %2;" : "=f"(r.x), "=f"(r.y) : "l"(d)); return r;
}
__device__ __forceinline__ float bnl(float x, float s, float h) {
    float o = fmaf(x, s, h);
    return o > 0.f ? o : 0.01f * o;
}

__global__ __launch_bounds__(256) void gemm_kernel(const float* __restrict__ A,
        const float* __restrict__ W, const float* __restrict__ bias,
        float* __restrict__ C, int M, int N, int K, int act,
        const float* __restrict__ scA, const float* __restrict__ shA) {
    __shared__ float As[16][68];
    __shared__ float Bs[16][68];
    const int tid = threadIdx.x;
    const int n0 = blockIdx.x * 64;
    const int m0 = blockIdx.y * 64;
    const int trow = tid >> 4;
    const int tcol = tid & 15;
    const int lm = tid >> 2;
    const int lk = (tid & 3) * 4;

    ull acc[4][2];
    #pragma unroll
    for (int r = 0; r < 4; r++) { acc[r][0] = 0ull; acc[r][1] = 0ull; }

    for (int kk = 0; kk < K; kk += 16) {
        float4 va = *(const float4*)&A[(size_t)(m0 + lm) * K + kk + lk];
        if (scA) {
            int f = kk + lk;
            va.x = bnl(va.x, scA[f+0], shA[f+0]);
            va.y = bnl(va.y, scA[f+1], shA[f+1]);
            va.z = bnl(va.z, scA[f+2], shA[f+2]);
            va.w = bnl(va.w, scA[f+3], shA[f+3]);
        }
        float4 vb = *(const float4*)&W[(size_t)(n0 + lm) * K + kk + lk];
        As[lk+0][lm] = va.x; As[lk+1][lm] = va.y; As[lk+2][lm] = va.z; As[lk+3][lm] = va.w;
        Bs[lk+0][lm] = vb.x; Bs[lk+1][lm] = vb.y; Bs[lk+2][lm] = vb.z; Bs[lk+3][lm] = vb.w;
        __syncthreads();
        #pragma unroll
        for (int k = 0; k < 16; k++) {
            float4 a = *(const float4*)&As[k][trow * 4];
            const ull* bp = (const ull*)&Bs[k][tcol * 4];
            ull b0 = bp[0], b1 = bp[1];
            ull a0 = pk2(a.x, a.x), a1 = pk2(a.y, a.y);
            ull a2 = pk2(a.z, a.z), a3 = pk2(a.w, a.w);
            fma2(acc[0][0], a0, b0); fma2(acc[0][1], a0, b1);
            fma2(acc[1][0], a1, b0); fma2(acc[1][1], a1, b1);
            fma2(acc[2][0], a2, b0); fma2(acc[2][1], a2, b1);
            fma2(acc[3][0], a3, b0); fma2(acc[3][1], a3, b1);
        }
        __syncthreads();
    }

    #pragma unroll
    for (int r = 0; r < 4; r++) {
        int m = m0 + trow * 4 + r;
        int n = n0 + tcol * 4;
        float2 v0 = unpk2(acc[r][0]);
        float2 v1 = unpk2(acc[r][1]);
        float o0 = v0.x + bias[n+0];
        float o1 = v0.y + bias[n+1];
        float o2 = v1.x + bias[n+2];
        float o3 = v1.y + bias[n+3];
        if (act == 1) {
            o0 = fmaxf(o0, 0.f); o1 = fmaxf(o1, 0.f);
            o2 = fmaxf(o2, 0.f); o3 = fmaxf(o3, 0.f);
        }
        *(float4*)&C[(size_t)m * N + n] = make_float4(o0, o1, o2, o3);
    }
}

// ============================================================================
// reparameterize + emit mu/logvar to output tail
// ============================================================================
__global__ void reparam_kernel(const float* __restrict__ mu, const float* __restrict__ lv,
                               const float* __restrict__ eps, float* __restrict__ z,
                               float* __restrict__ out) {
    int i = blockIdx.x * 256 + threadIdx.x;
    float m = mu[i], l = lv[i];
    z[i] = m + eps[i] * expf(0.5f * l);
    out[OFF_MU + i] = m;
    out[OFF_LV + i] = l;
}

// ============================================================================
// GRU recurrence: 128 CTAs x 384 thr, 2 rows/CTA.
// Whh register-resident, packed per-k-pair into 64 ull regs; matvec via
// fma.rn.f32x2 over (even,odd) k pairs; h rows broadcast from smem as ull2.
// ============================================================================
__global__ __launch_bounds__(384, 1) void gru_kernel(const float* __restrict__ xp,
        const float* __restrict__ Whh, const float* __restrict__ bhh,
        float* __restrict__ h2all) {
    __shared__ __align__(16) float h_a[128];
    __shared__ __align__(16) float h_b[128];
    __shared__ float hp_s[768];
    __shared__ float xp_s[768];
    const int j = threadIdx.x;             // 0..383 (gate-unit)
    const int row0 = blockIdx.x * 2;

    ull w2[64];                            // (w[2k], w[2k+1]) pairs, registers
    #pragma unroll
    for (int kq = 0; kq < 32; kq++) {
        float4 v = *(const float4*)&Whh[(size_t)j * GH + kq * 4];
        w2[2*kq+0] = pk2(v.x, v.y);
        w2[2*kq+1] = pk2(v.z, v.w);
    }
    const float bh = bhh[j];
    xp_s[j]       = xp[(size_t)row0 * 384 + j];
    xp_s[384 + j] = xp[(size_t)(row0 + 1) * 384 + j];
    if (j < 128) { h_a[j] = 0.0f; h_b[j] = 0.0f; }
    __syncthreads();

    for (int t = 0; t < SEQ; t++) {
        ull accA = 0ull, accB = 0ull;      // (even-k sum, odd-k sum) per row
        #pragma unroll
        for (int kq = 0; kq < 32; kq++) {
            ulonglong2 ha = *(const ulonglong2*)&h_a[kq * 4];
            ulonglong2 hb = *(const ulonglong2*)&h_b[kq * 4];
            fma2(accA, w2[2*kq+0], ha.x);
            fma2(accA, w2[2*kq+1], ha.y);
            fma2(accB, w2[2*kq+0], hb.x);
            fma2(accB, w2[2*kq+1], hb.y);
        }
        float2 pa = unpk2(accA);
        float2 pb = unpk2(accB);
        hp_s[j]       = pa.x + pa.y + bh;
        hp_s[384 + j] = pb.x + pb.y + bh;
        __syncthreads();
        if (j < 256) {
            int r = j >> 7, u = j & 127;
            const float* hp = hp_s + r * 384;
            const float* xq = xp_s + r * 384;
            float rg = 1.0f / (1.0f + expf(-(xq[u]       + hp[u])));
            float zg = 1.0f / (1.0f + expf(-(xq[128 + u] + hp[128 + u])));
            float nn = tanhf(xq[256 + u] + rg * hp[256 + u]);
            float hold = r ? h_b[u] : h_a[u];
            float hnew = (1.0f - zg) * nn + zg * hold;
            if (r) h_b[u] = hnew; else h_a[u] = hnew;
            h2all[((size_t)t * BATCH + row0 + r) * GH + u] = hnew;
        }
        __syncthreads();
    }
}

// ============================================================================
// final argmax reduce over 4 partials + one-hot write
// ============================================================================
__global__ __launch_bounds__(256) void argmax_final(const float2* __restrict__ amp,
                                                    float* __restrict__ out) {
    int row  = blockIdx.x * 8 + (threadIdx.x >> 5);   // < 32768
    int lane = threadIdx.x & 31;
    float best = -1e30f; int bi = 0x7fffffff;
    if (lane < 4) {
        float2 e = amp[(size_t)row * 4 + lane];
        best = e.x; bi = __float_as_int(e.y);
    }
    #pragma unroll
    for (int o = 1; o < 4; o <<= 1) {
        float ov = __shfl_xor_sync(0xffffffffu, best, o);
        int   oi = __shfl_xor_sync(0xffffffffu, bi, o);
        if (ov > best || (ov == best && oi < bi)) { best = ov; bi = oi; }
    }
    bi = __shfl_sync(0xffffffffu, bi, 0);
    int t = row >> 8, b = row & 255;
    float* op = out + (size_t)b * (SEQ * VOCAB) + (size_t)t * VOCAB;
    #pragma unroll
    for (int q = 0; q < 4; q++) {
        int c = lane * 16 + q * 4;
        *(float4*)&op[c] = make_float4(c == bi ? 1.f : 0.f, c + 1 == bi ? 1.f : 0.f,
                                       c + 2 == bi ? 1.f : 0.f, c + 3 == bi ? 1.f : 0.f);
    }
}

// ============================================================================
// launcher
// ============================================================================
extern "C" void kernel_launch(void* const* d_in, const int* in_sizes, int n_in,
                              void* d_out, int out_size) {
    (void)in_sizes; (void)n_in; (void)out_size;
    const float* x    = (const float*)d_in[0];
    const float* eps  = (const float*)d_in[1];
    const float* W0   = (const float*)d_in[2];
    const float* b0   = (const float*)d_in[3];
    const float* g0   = (const float*)d_in[4];
    const float* be0  = (const float*)d_in[5];
    const float* W1   = (const float*)d_in[6];
    const float* b1   = (const float*)d_in[7];
    const float* g1   = (const float*)d_in[8];
    const float* be1  = (const float*)d_in[9];
    const float* W2   = (const float*)d_in[10];
    const float* b2   = (const float*)d_in[11];
    const float* g2   = (const float*)d_in[12];
    const float* be2  = (const float*)d_in[13];
    const float* Wout = (const float*)d_in[14];
    const float* bout = (const float*)d_in[15];
    const float* Wmu  = (const float*)d_in[16];
    const float* bmu  = (const float*)d_in[17];
    const float* Wlv  = (const float*)d_in[18];
    const float* blv  = (const float*)d_in[19];
    const float* Wih  = (const float*)d_in[20];
    const float* bih  = (const float*)d_in[21];
    const float* Whh  = (const float*)d_in[22];
    const float* bhh  = (const float*)d_in[23];
    const float* Wfc  = (const float*)d_in[24];
    const float* bfc  = (const float*)d_in[25];
    float* out = (float*)d_out;

    float* S = nullptr;
    cudaGetSymbolAddress((void**)&S, g_scratch);

    cudaFuncSetAttribute(gemm_mma, cudaFuncAttributeMaxDynamicSharedMemorySize, MMA_SMEM);

    // --- encoder layer 0: fp16-split mma, split-K=9 (144 CTAs = 1 wave) ---
    gemm_mma<<<dim3(8, 2, GSPLITS), 256, MMA_SMEM>>>(x, W0, nullptr, S + S_WS,
                                                     K0, N0, TCHUNKS0, GSPLITS,
                                                     (size_t)BATCH * N0, nullptr);
    reduce_bias_kernel<<<1024, 256>>>(S + S_WS, b0, S + S_H0);
    bn_stats_kernel<<<4, 256>>>(S + S_H0, g0, be0, S + S_SCALE, S + S_SHIFT, 1024);

    // --- encoder layer 1: 1024 -> 512 (BN0+lrelu fused into A-load) ---
    gemm_kernel<<<dim3(8, 4), 256>>>(S + S_H0, W1, b1, S + S_H1, 256, 512, 1024, 0,
                                     S + S_SCALE, S + S_SHIFT);
    bn_stats_kernel<<<2, 256>>>(S + S_H1, g1, be1, S + S_SCALE, S + S_SHIFT, 512);

    // --- encoder layer 2: 512 -> 256 (BN1 fused) ---
    gemm_kernel<<<dim3(4, 4), 256>>>(S + S_H1, W2, b2, S + S_H2B, 256, 256, 512, 0,
                                     S + S_SCALE, S + S_SHIFT);
    bn_stats_kernel<<<1, 256>>>(S + S_H2B, g2, be2, S + S_SCALE, S + S_SHIFT, 256);

    // --- out layer (BN2 fused on A, relu on out), mu, logvar ---
    gemm_kernel<<<dim3(2, 4), 256>>>(S + S_H2B, Wout, bout, S + S_HENC, 256, 128, 256, 1,
                                     S + S_SCALE, S + S_SHIFT);
    gemm_kernel<<<dim3(2, 4), 256>>>(S + S_HENC, Wmu, bmu, S + S_MU, 256, 128, 128, 0,
                                     nullptr, nullptr);
    gemm_kernel<<<dim3(2, 4), 256>>>(S + S_HENC, Wlv, blv, S + S_LV, 256, 128, 128, 0,
                                     nullptr, nullptr);

    // --- reparameterize ---
    reparam_kernel<<<128, 256>>>(S + S_MU, S + S_LV, eps, S + S_Z, out);

    // --- GRU input projection ---
    gemm_kernel<<<dim3(6, 4), 256>>>(S + S_Z, Wih, bih, S + S_XP, 256, 384, 128, 0,
                                     nullptr, nullptr);

    // --- GRU recurrence (register weights, f32x2) ---
    gru_kernel<<<128, 384>>>(S + S_XP, Whh, bhh, S + S_H2ALL);

    // --- logits GEMM with fused bias+argmax partials ---
    gemm_mma<<<dim3(4, 256, 1), 256, MMA_SMEM>>>(S + S_H2ALL, Wfc, bfc, nullptr,
                                                 GH, 0, 4, 1, 0,
                                                 (float2*)(S + S_AMP));
    argmax_final<<<4096, 256>>>((const float2*)(S + S_AMP), out);
}

// round 11
// speedup vs baseline: 3.2011x; 1.1221x over previous
#include <cuda_runtime.h>
#include <math.h>
#include <stdint.h>

typedef unsigned long long ull;

#define BATCH 256
#define SEQ   128
#define VOCAB 512
#define GH    128
#define K0    65536
#define N0    1024
#define GSPLITS 9
#define TCHUNKS0 2048          /* K0/32 */

#define OFF_MU (BATCH*SEQ*VOCAB)
#define OFF_LV (OFF_MU + BATCH*GH)

// ---- scratch layout (single static __device__ array) ----
#define S_WS     0u                        /* up to 9 x 256 x 1024 partials */
#define S_H0     (S_WS + 2359296u)         /* 256x1024 (raw, pre-BN) */
#define S_H1     (S_H0 + 262144u)          /* 256x512  (raw) */
#define S_H2B    (S_H1 + 131072u)          /* 256x256  (raw) */
#define S_HENC   (S_H2B + 65536u)          /* 256x128  */
#define S_MU     (S_HENC + 32768u)
#define S_LV     (S_MU + 32768u)
#define S_Z      (S_LV + 32768u)
#define S_XP     (S_Z + 32768u)            /* 256x384  */
#define S_H2ALL  (S_XP + 98304u)           /* 32768x128 */
#define S_AMP    (S_H2ALL + 4194304u)      /* 32768x4 float2 */
#define S_SCALE  (S_AMP + 262144u)
#define S_SHIFT  (S_SCALE + 1024u)
#define S_TOTAL  (S_SHIFT + 1024u)

__device__ float g_scratch[S_TOTAL];

// ============================================================================
// helpers
// ============================================================================
__device__ __forceinline__ uint32_t packh2(float lo, float hi) {
    uint32_t r; asm("cvt.rn.f16x2.f32 %0, %1, %2;" : "=r"(r) : "f"(hi), "f"(lo)); return r;
}

// truncation split: hi = top 11 significand bits (exact in fp16),
// lo = (v - hi) * 2048 (exact fp32 sub; fp16 keeps top 11 of remainder).
__device__ __forceinline__ void split11(float v, float& hi, float& lo) {
    hi = __uint_as_float(__float_as_uint(v) & 0xFFFFE000u);
    lo = __fmul_rn(__fsub_rn(v, hi), 2048.0f);
}

__device__ __forceinline__ float bnl(float x, float s, float h) {
    float o = fmaf(x, s, h);
    return o > 0.f ? o : 0.01f * o;
}
__device__ __forceinline__ void bnl4(float4& v, int f,
                                     const float* __restrict__ sc,
                                     const float* __restrict__ sh) {
    v.x = bnl(v.x, sc[f+0], sh[f+0]);
    v.y = bnl(v.y, sc[f+1], sh[f+1]);
    v.z = bnl(v.z, sc[f+2], sh[f+2]);
    v.w = bnl(v.w, sc[f+3], sh[f+3]);
}

#define MMA_F16(acc, af, bf) asm volatile( \
    "mma.sync.aligned.m16n8k16.row.col.f32.f16.f16.f32 " \
    "{%0,%1,%2,%3}, {%4,%5,%6,%7}, {%8,%9}, {%0,%1,%2,%3};" \
    : "+f"((acc)[0]), "+f"((acc)[1]), "+f"((acc)[2]), "+f"((acc)[3]) \
    : "r"((af)[0]), "r"((af)[1]), "r"((af)[2]), "r"((af)[3]), \
      "r"((bf)[0]), "r"((bf)[1]))

#define PSTRIDE 20
#define PLANE   (128 * PSTRIDE)
#define BUFU32  (4 * PLANE)
#define MMA_SMEM (2 * BUFU32 * 4)          /* 81920 bytes */

// ============================================================================
// FP16-split tensor GEMM via mma.sync m16n8k16, tile 128x128, BK=32.
//   optional fused BN+LeakyReLU on A columns (scA/shA)
//   amax == null: nsplit>1 -> partials at C + z*splitStride
//                 nsplit==1 -> direct write (+bias if given, relu if act)
//   amax != null: add bias, per-row argmax over this CTA's 128 cols
// ============================================================================
__global__ __launch_bounds__(256, 1) void gemm_mma(const float* __restrict__ A,
        const float* __restrict__ B, const float* __restrict__ bias,
        float* __restrict__ C, int ldA, int ldc, int tchunks, int nsplit,
        size_t splitStride, float2* __restrict__ amax,
        const float* __restrict__ scA, const float* __restrict__ shA, int act) {
    extern __shared__ float smf[];
    uint32_t* smu = (uint32_t*)smf;
    const int tid  = threadIdx.x;
    const int lane = tid & 31;
    const int g    = lane >> 2;
    const int t    = lane & 3;
    const int warp = tid >> 5;
    const int m0w  = (warp >> 2) * 64;
    const int n0w  = (warp & 3) * 32;
    const int n0   = blockIdx.x * 128;
    const int m0   = blockIdx.y * 128;

    const int cs = (int)(((long long)blockIdx.z * tchunks) / nsplit);
    const int ce = (int)(((long long)(blockIdx.z + 1) * tchunks) / nsplit);
    const int nchunks = ce - cs;
    const int kbase = cs * 32;

    const int rb = tid >> 3;
    const int q  = tid & 7;

    float accH[4][4][4], accL[4][4][4];
    #pragma unroll
    for (int mt = 0; mt < 4; mt++)
        #pragma unroll
        for (int nt = 0; nt < 4; nt++)
            #pragma unroll
            for (int i = 0; i < 4; i++) { accH[mt][nt][i] = 0.f; accL[mt][nt][i] = 0.f; }

    float4 stA[4], stB[4];

    // prologue: stage + convert chunk 0
    #pragma unroll
    for (int j = 0; j < 4; j++) {
        stA[j] = *(const float4*)&A[(size_t)(m0 + rb + 32*j) * ldA + kbase + q*4];
        if (scA) bnl4(stA[j], kbase + q*4, scA, shA);
        stB[j] = *(const float4*)&B[(size_t)(n0 + rb + 32*j) * ldA + kbase + q*4];
    }
    {
        uint32_t* ahi = smu;           uint32_t* alo = smu + PLANE;
        uint32_t* bhi = smu + 2*PLANE; uint32_t* blo = smu + 3*PLANE;
        #pragma unroll
        for (int j = 0; j < 4; j++) {
            int off = (rb + 32*j) * PSTRIDE + 2*q;
            float4 v = stA[j];
            float hx,lx,hy,ly,hz,lz,hw,lw;
            split11(v.x,hx,lx); split11(v.y,hy,ly); split11(v.z,hz,lz); split11(v.w,hw,lw);
            *(uint2*)&ahi[off] = make_uint2(packh2(hx,hy), packh2(hz,hw));
            *(uint2*)&alo[off] = make_uint2(packh2(lx,ly), packh2(lz,lw));
            v = stB[j];
            split11(v.x,hx,lx); split11(v.y,hy,ly); split11(v.z,hz,lz); split11(v.w,hw,lw);
            *(uint2*)&bhi[off] = make_uint2(packh2(hx,hy), packh2(hz,hw));
            *(uint2*)&blo[off] = make_uint2(packh2(lx,ly), packh2(lz,lw));
        }
    }
    __syncthreads();

    for (int c = 0; c < nchunks; c++) {
        if (c + 1 < nchunks) {
            int kp = kbase + (c + 1) * 32;
            #pragma unroll
            for (int j = 0; j < 4; j++) {
                stA[j] = *(const float4*)&A[(size_t)(m0 + rb + 32*j) * ldA + kp + q*4];
                if (scA) bnl4(stA[j], kp + q*4, scA, shA);
                stB[j] = *(const float4*)&B[(size_t)(n0 + rb + 32*j) * ldA + kp + q*4];
            }
        }

        const uint32_t* base = smu + (c & 1) * BUFU32;
        const uint32_t* pAhi = base;
        const uint32_t* pAlo = base + PLANE;
        const uint32_t* pBhi = base + 2*PLANE;
        const uint32_t* pBlo = base + 3*PLANE;

        #pragma unroll
        for (int ks = 0; ks < 2; ks++) {
            const int kk = ks * 8;
            uint32_t aH[4][4], aL[4][4], bH[4][2], bL[4][2];
            #pragma unroll
            for (int mt = 0; mt < 4; mt++) {
                int ro = (m0w + mt*16 + g) * PSTRIDE + kk + t;
                aH[mt][0] = pAhi[ro];
                aH[mt][1] = pAhi[ro + 8*PSTRIDE];
                aH[mt][2] = pAhi[ro + 4];
                aH[mt][3] = pAhi[ro + 8*PSTRIDE + 4];
                aL[mt][0] = pAlo[ro];
                aL[mt][1] = pAlo[ro + 8*PSTRIDE];
                aL[mt][2] = pAlo[ro + 4];
                aL[mt][3] = pAlo[ro + 8*PSTRIDE + 4];
            }
            #pragma unroll
            for (int nt = 0; nt < 4; nt++) {
                int rn = (n0w + nt*8 + g) * PSTRIDE + kk + t;
                bH[nt][0] = pBhi[rn];
                bH[nt][1] = pBhi[rn + 4];
                bL[nt][0] = pBlo[rn];
                bL[nt][1] = pBlo[rn + 4];
            }
            #pragma unroll
            for (int mt = 0; mt < 4; mt++)
                #pragma unroll
                for (int nt = 0; nt < 4; nt++) {
                    MMA_F16(accH[mt][nt], aH[mt], bH[nt]);
                    MMA_F16(accL[mt][nt], aH[mt], bL[nt]);
                    MMA_F16(accL[mt][nt], aL[mt], bH[nt]);
                }
        }

        if (c + 1 < nchunks) {
            uint32_t* bb = smu + ((c + 1) & 1) * BUFU32;
            uint32_t* ahi = bb;           uint32_t* alo = bb + PLANE;
            uint32_t* bhi = bb + 2*PLANE; uint32_t* blo = bb + 3*PLANE;
            #pragma unroll
            for (int j = 0; j < 4; j++) {
                int off = (rb + 32*j) * PSTRIDE + 2*q;
                float4 v = stA[j];
                float hx,lx,hy,ly,hz,lz,hw,lw;
                split11(v.x,hx,lx); split11(v.y,hy,ly); split11(v.z,hz,lz); split11(v.w,hw,lw);
                *(uint2*)&ahi[off] = make_uint2(packh2(hx,hy), packh2(hz,hw));
                *(uint2*)&alo[off] = make_uint2(packh2(lx,ly), packh2(lz,lw));
                v = stB[j];
                split11(v.x,hx,lx); split11(v.y,hy,ly); split11(v.z,hz,lz); split11(v.w,hw,lw);
                *(uint2*)&bhi[off] = make_uint2(packh2(hx,hy), packh2(hz,hw));
                *(uint2*)&blo[off] = make_uint2(packh2(lx,ly), packh2(lz,lw));
            }
        }
        __syncthreads();
    }

    const float inv2048 = 1.0f / 2048.0f;

    if (amax == nullptr) {
        float* Cp = C + (size_t)blockIdx.z * splitStride;
        #pragma unroll
        for (int mt = 0; mt < 4; mt++) {
            #pragma unroll
            for (int nt = 0; nt < 4; nt++) {
                int row = m0 + m0w + mt*16 + g;
                int col = n0 + n0w + nt*8 + 2*t;
                float o0 = accH[mt][nt][0] + accL[mt][nt][0]*inv2048;
                float o1 = accH[mt][nt][1] + accL[mt][nt][1]*inv2048;
                float o2 = accH[mt][nt][2] + accL[mt][nt][2]*inv2048;
                float o3 = accH[mt][nt][3] + accL[mt][nt][3]*inv2048;
                if (bias) {
                    float bx = bias[col], by = bias[col+1];
                    o0 += bx; o1 += by; o2 += bx; o3 += by;
                }
                if (act) {
                    o0 = fmaxf(o0, 0.f); o1 = fmaxf(o1, 0.f);
                    o2 = fmaxf(o2, 0.f); o3 = fmaxf(o3, 0.f);
                }
                *(float2*)&Cp[(size_t)row * ldc + col] = make_float2(o0, o1);
                *(float2*)&Cp[(size_t)(row + 8) * ldc + col] = make_float2(o2, o3);
            }
        }
    } else {
        float2* sred = (float2*)smf;
        const int warp_n = warp & 3;
        #pragma unroll
        for (int half = 0; half < 2; half++) {
            #pragma unroll
            for (int mt = 0; mt < 4; mt++) {
                int rloc = m0w + mt*16 + g + half*8;
                float best = -1e30f; int bidx = 0;
                #pragma unroll
                for (int nt = 0; nt < 4; nt++) {
                    #pragma unroll
                    for (int e = 0; e < 2; e++) {
                        int col = n0 + n0w + nt*8 + 2*t + e;
                        float v = accH[mt][nt][half*2 + e] + accL[mt][nt][half*2 + e]*inv2048
                                  + bias[col];
                        if (v > best) { best = v; bidx = col; }
                    }
                }
                #pragma unroll
                for (int o = 1; o < 4; o <<= 1) {
                    float ov = __shfl_xor_sync(0xffffffffu, best, o);
                    int   oi = __shfl_xor_sync(0xffffffffu, bidx, o);
                    if (ov > best || (ov == best && oi < bidx)) { best = ov; bidx = oi; }
                }
                if (t == 0) sred[rloc * 4 + warp_n] = make_float2(best, __int_as_float(bidx));
            }
        }
        __syncthreads();
        if (tid < 128) {
            float best = -1e30f; int bidx = 0x7fffffff;
            #pragma unroll
            for (int wn = 0; wn < 4; wn++) {
                float2 e = sred[tid * 4 + wn];
                int ei = __float_as_int(e.y);
                if (e.x > best || (e.x == best && ei < bidx)) { best = e.x; bidx = ei; }
            }
            amax[(size_t)(m0 + tid) * 4 + blockIdx.x] = make_float2(best, __int_as_float(bidx));
        }
    }
}

// generic deterministic split-K reduce + bias (+optional relu)
__global__ __launch_bounds__(256) void reduce_gen(const float* __restrict__ ws,
        const float* __restrict__ bias, float* __restrict__ out,
        int nsplit, int strideElems, int nmask, int act) {
    int i = blockIdx.x * 256 + threadIdx.x;
    float s = 0.0f;
    for (int sp = 0; sp < nsplit; sp++) s += ws[(size_t)sp * strideElems + i];
    s += bias[i & nmask];
    if (act) s = fmaxf(s, 0.f);
    out[i] = s;
}

// ============================================================================
// BatchNorm stats (scale/shift); apply is fused into the consumer GEMM
// ============================================================================
__global__ void bn_stats_kernel(const float* __restrict__ h, const float* __restrict__ g,
                                const float* __restrict__ be, float* __restrict__ scale,
                                float* __restrict__ shift, int N) {
    int f = blockIdx.x * 256 + threadIdx.x;
    if (f >= N) return;
    float s = 0.f, ss = 0.f;
    #pragma unroll 4
    for (int b = 0; b < BATCH; b++) {
        float v = h[(size_t)b * N + f];
        s += v; ss += v * v;
    }
    float mean = s * (1.0f / BATCH);
    float var = ss * (1.0f / BATCH) - mean * mean;
    float sc = rsqrtf(var + 1e-5f) * g[f];
    scale[f] = sc;
    shift[f] = be[f] - mean * sc;
}

// ============================================================================
// fp32x2 GEMM for small layers; dual-output via blockIdx.z
// ============================================================================
__device__ __forceinline__ void fma2(ull &d, ull a, ull b) {
    asm("fma.rn.f32x2 %0, %1, %2, %0;" : "+l"(d) : "l"(a), "l"(b));
}
__device__ __forceinline__ ull pk2(float x, float y) {
    ull d; asm("mov.b64 %0, {%1, %2};" : "=l"(d) : "f"(x), "f"(y)); return d;
}
__device__ __forceinline__ float2 unpk2(ull d) {
    float2 r; asm("mov.b64 {%0, %1}, %2;" : "=f"(r.x), "=f"(r.y) : "l"(d)); return r;
}

__global__ __launch_bounds__(256) void gemm_kernel(const float* __restrict__ A,
        const float* __restrict__ W, const float* __restrict__ bias,
        float* __restrict__ C, int M, int N, int K, int act,
        const float* __restrict__ W2, const float* __restrict__ b2,
        float* __restrict__ C2) {
    if (blockIdx.z == 1) { W = W2; bias = b2; C = C2; }
    __shared__ float As[16][68];
    __shared__ float Bs[16][68];
    const int tid = threadIdx.x;
    const int n0 = blockIdx.x * 64;
    const int m0 = blockIdx.y * 64;
    const int trow = tid >> 4;
    const int tcol = tid & 15;
    const int lm = tid >> 2;
    const int lk = (tid & 3) * 4;

    ull acc[4][2];
    #pragma unroll
    for (int r = 0; r < 4; r++) { acc[r][0] = 0ull; acc[r][1] = 0ull; }

    for (int kk = 0; kk < K; kk += 16) {
        float4 va = *(const float4*)&A[(size_t)(m0 + lm) * K + kk + lk];
        float4 vb = *(const float4*)&W[(size_t)(n0 + lm) * K + kk + lk];
        As[lk+0][lm] = va.x; As[lk+1][lm] = va.y; As[lk+2][lm] = va.z; As[lk+3][lm] = va.w;
        Bs[lk+0][lm] = vb.x; Bs[lk+1][lm] = vb.y; Bs[lk+2][lm] = vb.z; Bs[lk+3][lm] = vb.w;
        __syncthreads();
        #pragma unroll
        for (int k = 0; k < 16; k++) {
            float4 a = *(const float4*)&As[k][trow * 4];
            const ull* bp = (const ull*)&Bs[k][tcol * 4];
            ull b0 = bp[0], b1 = bp[1];
            ull a0 = pk2(a.x, a.x), a1 = pk2(a.y, a.y);
            ull a2 = pk2(a.z, a.z), a3 = pk2(a.w, a.w);
            fma2(acc[0][0], a0, b0); fma2(acc[0][1], a0, b1);
            fma2(acc[1][0], a1, b0); fma2(acc[1][1], a1, b1);
            fma2(acc[2][0], a2, b0); fma2(acc[2][1], a2, b1);
            fma2(acc[3][0], a3, b0); fma2(acc[3][1], a3, b1);
        }
        __syncthreads();
    }

    #pragma unroll
    for (int r = 0; r < 4; r++) {
        int m = m0 + trow * 4 + r;
        int n = n0 + tcol * 4;
        float2 v0 = unpk2(acc[r][0]);
        float2 v1 = unpk2(acc[r][1]);
        float o0 = v0.x + bias[n+0];
        float o1 = v0.y + bias[n+1];
        float o2 = v1.x + bias[n+2];
        float o3 = v1.y + bias[n+3];
        if (act == 1) {
            o0 = fmaxf(o0, 0.f); o1 = fmaxf(o1, 0.f);
            o2 = fmaxf(o2, 0.f); o3 = fmaxf(o3, 0.f);
        }
        *(float4*)&C[(size_t)m * N + n] = make_float4(o0, o1, o2, o3);
    }
}

// ============================================================================
// reparameterize + emit mu/logvar to output tail
// ============================================================================
__global__ void reparam_kernel(const float* __restrict__ mu, const float* __restrict__ lv,
                               const float* __restrict__ eps, float* __restrict__ z,
                               float* __restrict__ out) {
    int i = blockIdx.x * 256 + threadIdx.x;
    float m = mu[i], l = lv[i];
    z[i] = m + eps[i] * expf(0.5f * l);
    out[OFF_MU + i] = m;
    out[OFF_LV + i] = l;
}

// ============================================================================
// GRU recurrence: 128 CTAs x 384 thr, 2 rows/CTA, register weights + f32x2
// ============================================================================
__global__ __launch_bounds__(384, 1) void gru_kernel(const float* __restrict__ xp,
        const float* __restrict__ Whh, const float* __restrict__ bhh,
        float* __restrict__ h2all) {
    __shared__ __align__(16) float h_a[128];
    __shared__ __align__(16) float h_b[128];
    __shared__ float hp_s[768];
    __shared__ float xp_s[768];
    const int j = threadIdx.x;
    const int row0 = blockIdx.x * 2;

    ull w2[64];
    #pragma unroll
    for (int kq = 0; kq < 32; kq++) {
        float4 v = *(const float4*)&Whh[(size_t)j * GH + kq * 4];
        w2[2*kq+0] = pk2(v.x, v.y);
        w2[2*kq+1] = pk2(v.z, v.w);
    }
    const float bh = bhh[j];
    xp_s[j]       = xp[(size_t)row0 * 384 + j];
    xp_s[384 + j] = xp[(size_t)(row0 + 1) * 384 + j];
    if (j < 128) { h_a[j] = 0.0f; h_b[j] = 0.0f; }
    __syncthreads();

    for (int t = 0; t < SEQ; t++) {
        ull accA = 0ull, accB = 0ull;
        #pragma unroll
        for (int kq = 0; kq < 32; kq++) {
            ulonglong2 ha = *(const ulonglong2*)&h_a[kq * 4];
            ulonglong2 hb = *(const ulonglong2*)&h_b[kq * 4];
            fma2(accA, w2[2*kq+0], ha.x);
            fma2(accA, w2[2*kq+1], ha.y);
            fma2(accB, w2[2*kq+0], hb.x);
            fma2(accB, w2[2*kq+1], hb.y);
        }
        float2 pa = unpk2(accA);
        float2 pb = unpk2(accB);
        hp_s[j]       = pa.x + pa.y + bh;
        hp_s[384 + j] = pb.x + pb.y + bh;
        __syncthreads();
        if (j < 256) {
            int r = j >> 7, u = j & 127;
            const float* hp = hp_s + r * 384;
            const float* xq = xp_s + r * 384;
            float rg = 1.0f / (1.0f + expf(-(xq[u]       + hp[u])));
            float zg = 1.0f / (1.0f + expf(-(xq[128 + u] + hp[128 + u])));
            float nn = tanhf(xq[256 + u] + rg * hp[256 + u]);
            float hold = r ? h_b[u] : h_a[u];
            float hnew = (1.0f - zg) * nn + zg * hold;
            if (r) h_b[u] = hnew; else h_a[u] = hnew;
            h2all[((size_t)t * BATCH + row0 + r) * GH + u] = hnew;
        }
        __syncthreads();
    }
}

// ============================================================================
// final argmax reduce over 4 partials + one-hot write
// ============================================================================
__global__ __launch_bounds__(256) void argmax_final(const float2* __restrict__ amp,
                                                    float* __restrict__ out) {
    int row  = blockIdx.x * 8 + (threadIdx.x >> 5);
    int lane = threadIdx.x & 31;
    float best = -1e30f; int bi = 0x7fffffff;
    if (lane < 4) {
        float2 e = amp[(size_t)row * 4 + lane];
        best = e.x; bi = __float_as_int(e.y);
    }
    #pragma unroll
    for (int o = 1; o < 4; o <<= 1) {
        float ov = __shfl_xor_sync(0xffffffffu, best, o);
        int   oi = __shfl_xor_sync(0xffffffffu, bi, o);
        if (ov > best || (ov == best && oi < bi)) { best = ov; bi = oi; }
    }
    bi = __shfl_sync(0xffffffffu, bi, 0);
    int t = row >> 8, b = row & 255;
    float* op = out + (size_t)b * (SEQ * VOCAB) + (size_t)t * VOCAB;
    #pragma unroll
    for (int q = 0; q < 4; q++) {
        int c = lane * 16 + q * 4;
        *(float4*)&op[c] = make_float4(c == bi ? 1.f : 0.f, c + 1 == bi ? 1.f : 0.f,
                                       c + 2 == bi ? 1.f : 0.f, c + 3 == bi ? 1.f : 0.f);
    }
}

// ============================================================================
// launcher
// ============================================================================
extern "C" void kernel_launch(void* const* d_in, const int* in_sizes, int n_in,
                              void* d_out, int out_size) {
    (void)in_sizes; (void)n_in; (void)out_size;
    const float* x    = (const float*)d_in[0];
    const float* eps  = (const float*)d_in[1];
    const float* W0   = (const float*)d_in[2];
    const float* b0   = (const float*)d_in[3];
    const float* g0   = (const float*)d_in[4];
    const float* be0  = (const float*)d_in[5];
    const float* W1   = (const float*)d_in[6];
    const float* b1   = (const float*)d_in[7];
    const float* g1   = (const float*)d_in[8];
    const float* be1  = (const float*)d_in[9];
    const float* W2   = (const float*)d_in[10];
    const float* b2   = (const float*)d_in[11];
    const float* g2   = (const float*)d_in[12];
    const float* be2  = (const float*)d_in[13];
    const float* Wout = (const float*)d_in[14];
    const float* bout = (const float*)d_in[15];
    const float* Wmu  = (const float*)d_in[16];
    const float* bmu  = (const float*)d_in[17];
    const float* Wlv  = (const float*)d_in[18];
    const float* blv  = (const float*)d_in[19];
    const float* Wih  = (const float*)d_in[20];
    const float* bih  = (const float*)d_in[21];
    const float* Whh  = (const float*)d_in[22];
    const float* bhh  = (const float*)d_in[23];
    const float* Wfc  = (const float*)d_in[24];
    const float* bfc  = (const float*)d_in[25];
    float* out = (float*)d_out;

    float* S = nullptr;
    cudaGetSymbolAddress((void**)&S, g_scratch);

    cudaFuncSetAttribute(gemm_mma, cudaFuncAttributeMaxDynamicSharedMemorySize, MMA_SMEM);

    // --- encoder layer 0: fp16-split mma, split-K=9 (144 CTAs = 1 wave) ---
    gemm_mma<<<dim3(8, 2, GSPLITS), 256, MMA_SMEM>>>(x, W0, nullptr, S + S_WS,
        K0, N0, TCHUNKS0, GSPLITS, (size_t)BATCH * N0, nullptr, nullptr, nullptr, 0);
    reduce_gen<<<1024, 256>>>(S + S_WS, b0, S + S_H0, GSPLITS, BATCH * N0, N0 - 1, 0);
    bn_stats_kernel<<<4, 256>>>(S + S_H0, g0, be0, S + S_SCALE, S + S_SHIFT, 1024);

    // --- encoder layer 1: 1024 -> 512, mma split-K=8 (BN0+lrelu fused on A) ---
    gemm_mma<<<dim3(4, 2, 8), 256, MMA_SMEM>>>(S + S_H0, W1, nullptr, S + S_WS,
        1024, 512, 32, 8, (size_t)BATCH * 512, nullptr, S + S_SCALE, S + S_SHIFT, 0);
    reduce_gen<<<512, 256>>>(S + S_WS, b1, S + S_H1, 8, BATCH * 512, 511, 0);
    bn_stats_kernel<<<2, 256>>>(S + S_H1, g1, be1, S + S_SCALE, S + S_SHIFT, 512);

    // --- encoder layer 2: 512 -> 256, mma split-K=4 (BN1 fused) ---
    gemm_mma<<<dim3(2, 2, 4), 256, MMA_SMEM>>>(S + S_H1, W2, nullptr, S + S_WS,
        512, 256, 16, 4, (size_t)BATCH * 256, nullptr, S + S_SCALE, S + S_SHIFT, 0);
    reduce_gen<<<256, 256>>>(S + S_WS, b2, S + S_H2B, 4, BATCH * 256, 255, 0);
    bn_stats_kernel<<<1, 256>>>(S + S_H2B, g2, be2, S + S_SCALE, S + S_SHIFT, 256);

    // --- out layer: 256 -> 128, mma split-K=4 (BN2 fused), relu in reduce ---
    gemm_mma<<<dim3(1, 2, 4), 256, MMA_SMEM>>>(S + S_H2B, Wout, nullptr, S + S_WS,
        256, 128, 8, 4, (size_t)BATCH * 128, nullptr, S + S_SCALE, S + S_SHIFT, 0);
    reduce_gen<<<128, 256>>>(S + S_WS, bout, S + S_HENC, 4, BATCH * 128, 127, 1);

    // --- mu & logvar in one dual-output launch ---
    gemm_kernel<<<dim3(2, 4, 2), 256>>>(S + S_HENC, Wmu, bmu, S + S_MU, 256, 128, 128, 0,
                                        Wlv, blv, S + S_LV);

    // --- reparameterize ---
    reparam_kernel<<<128, 256>>>(S + S_MU, S + S_LV, eps, S + S_Z, out);

    // --- GRU input projection ---
    gemm_kernel<<<dim3(6, 4, 1), 256>>>(S + S_Z, Wih, bih, S + S_XP, 256, 384, 128, 0,
                                        nullptr, nullptr, nullptr);

    // --- GRU recurrence ---
    gru_kernel<<<128, 384>>>(S + S_XP, Whh, bhh, S + S_H2ALL);

    // --- logits GEMM with fused bias+argmax partials ---
    gemm_mma<<<dim3(4, 256, 1), 256, MMA_SMEM>>>(S + S_H2ALL, Wfc, bfc, nullptr,
        GH, 0, 4, 1, 0, (float2*)(S + S_AMP), nullptr, nullptr, 0);
    argmax_final<<<4096, 256>>>((const float2*)(S + S_AMP), out);
}

// round 12
// speedup vs baseline: 3.4528x; 1.0786x over previous
#include <cuda_runtime.h>
#include <math.h>
#include <stdint.h>

typedef unsigned long long ull;

#define BATCH 256
#define SEQ   128
#define VOCAB 512
#define GH    128
#define K0    65536
#define N0    1024
#define GSPLITS 9
#define TCHUNKS0 2048          /* K0/32 */

#define OFF_MU (BATCH*SEQ*VOCAB)
#define OFF_LV (OFF_MU + BATCH*GH)

// ---- scratch layout (single static __device__ array) ----
#define S_WS     0u                        /* up to 16 x 256 x 512 / 9 x 256 x 1024 partials */
#define S_H0     (S_WS + 2359296u)         /* 256x1024 (raw, pre-BN) */
#define S_H1     (S_H0 + 262144u)          /* 256x512  (raw) */
#define S_H2B    (S_H1 + 131072u)          /* 256x256  (raw) */
#define S_HENC   (S_H2B + 65536u)          /* 256x128  */
#define S_MU     (S_HENC + 32768u)
#define S_LV     (S_MU + 32768u)
#define S_Z      (S_LV + 32768u)
#define S_XP     (S_Z + 32768u)            /* 256x384  */
#define S_H2ALL  (S_XP + 98304u)           /* 32768x128 */
#define S_AMP    (S_H2ALL + 4194304u)      /* 32768x4 float2 */
#define S_SCALE  (S_AMP + 262144u)
#define S_SHIFT  (S_SCALE + 1024u)
#define S_BNP    (S_SHIFT + 1024u)         /* 8 x 1024 partial sums */
#define S_BNQ    (S_BNP + 8192u)           /* 8 x 1024 partial sumsq */
#define S_TOTAL  (S_BNQ + 8192u)

__device__ float g_scratch[S_TOTAL];

// ============================================================================
// helpers
// ============================================================================
__device__ __forceinline__ uint32_t packh2(float lo, float hi) {
    uint32_t r; asm("cvt.rn.f16x2.f32 %0, %1, %2;" : "=r"(r) : "f"(hi), "f"(lo)); return r;
}

// truncation split: hi = top 11 significand bits (exact in fp16),
// lo = (v - hi) * 2048 (exact fp32 sub; fp16 keeps top 11 of remainder).
__device__ __forceinline__ void split11(float v, float& hi, float& lo) {
    hi = __uint_as_float(__float_as_uint(v) & 0xFFFFE000u);
    lo = __fmul_rn(__fsub_rn(v, hi), 2048.0f);
}

__device__ __forceinline__ float bnl(float x, float s, float h) {
    float o = fmaf(x, s, h);
    return o > 0.f ? o : 0.01f * o;
}
__device__ __forceinline__ void bnl4(float4& v, int f,
                                     const float* __restrict__ sc,
                                     const float* __restrict__ sh) {
    v.x = bnl(v.x, sc[f+0], sh[f+0]);
    v.y = bnl(v.y, sc[f+1], sh[f+1]);
    v.z = bnl(v.z, sc[f+2], sh[f+2]);
    v.w = bnl(v.w, sc[f+3], sh[f+3]);
}

#define MMA_F16(acc, af, bf) asm volatile( \
    "mma.sync.aligned.m16n8k16.row.col.f32.f16.f16.f32 " \
    "{%0,%1,%2,%3}, {%4,%5,%6,%7}, {%8,%9}, {%0,%1,%2,%3};" \
    : "+f"((acc)[0]), "+f"((acc)[1]), "+f"((acc)[2]), "+f"((acc)[3]) \
    : "r"((af)[0]), "r"((af)[1]), "r"((af)[2]), "r"((af)[3]), \
      "r"((bf)[0]), "r"((bf)[1]))

#define PSTRIDE 20
#define PLANE   (128 * PSTRIDE)
#define BUFU32  (4 * PLANE)
#define MMA_SMEM (2 * BUFU32 * 4)          /* 81920 bytes */
#define LOGITS_SMEM (16 * PLANE * 4 + 4096) /* 16 planes + sred = 167936 bytes */

// ============================================================================
// FP16-split tensor GEMM via mma.sync m16n8k16, tile 128x128, BK=32.
//   optional fused BN+LeakyReLU on A columns (scA/shA)
//   nsplit>1 -> partials at C + z*splitStride; nsplit==1 -> direct (+bias/relu)
// ============================================================================
__global__ __launch_bounds__(256, 1) void gemm_mma(const float* __restrict__ A,
        const float* __restrict__ B, const float* __restrict__ bias,
        float* __restrict__ C, int ldA, int ldc, int tchunks, int nsplit,
        size_t splitStride, const float* __restrict__ scA,
        const float* __restrict__ shA, int act) {
    extern __shared__ float smf[];
    uint32_t* smu = (uint32_t*)smf;
    const int tid  = threadIdx.x;
    const int lane = tid & 31;
    const int g    = lane >> 2;
    const int t    = lane & 3;
    const int warp = tid >> 5;
    const int m0w  = (warp >> 2) * 64;
    const int n0w  = (warp & 3) * 32;
    const int n0   = blockIdx.x * 128;
    const int m0   = blockIdx.y * 128;

    const int cs = (int)(((long long)blockIdx.z * tchunks) / nsplit);
    const int ce = (int)(((long long)(blockIdx.z + 1) * tchunks) / nsplit);
    const int nchunks = ce - cs;
    const int kbase = cs * 32;

    const int rb = tid >> 3;
    const int q  = tid & 7;

    float accH[4][4][4], accL[4][4][4];
    #pragma unroll
    for (int mt = 0; mt < 4; mt++)
        #pragma unroll
        for (int nt = 0; nt < 4; nt++)
            #pragma unroll
            for (int i = 0; i < 4; i++) { accH[mt][nt][i] = 0.f; accL[mt][nt][i] = 0.f; }

    float4 stA[4], stB[4];

    #pragma unroll
    for (int j = 0; j < 4; j++) {
        stA[j] = *(const float4*)&A[(size_t)(m0 + rb + 32*j) * ldA + kbase + q*4];
        if (scA) bnl4(stA[j], kbase + q*4, scA, shA);
        stB[j] = *(const float4*)&B[(size_t)(n0 + rb + 32*j) * ldA + kbase + q*4];
    }
    {
        uint32_t* ahi = smu;           uint32_t* alo = smu + PLANE;
        uint32_t* bhi = smu + 2*PLANE; uint32_t* blo = smu + 3*PLANE;
        #pragma unroll
        for (int j = 0; j < 4; j++) {
            int off = (rb + 32*j) * PSTRIDE + 2*q;
            float4 v = stA[j];
            float hx,lx,hy,ly,hz,lz,hw,lw;
            split11(v.x,hx,lx); split11(v.y,hy,ly); split11(v.z,hz,lz); split11(v.w,hw,lw);
            *(uint2*)&ahi[off] = make_uint2(packh2(hx,hy), packh2(hz,hw));
            *(uint2*)&alo[off] = make_uint2(packh2(lx,ly), packh2(lz,lw));
            v = stB[j];
            split11(v.x,hx,lx); split11(v.y,hy,ly); split11(v.z,hz,lz); split11(v.w,hw,lw);
            *(uint2*)&bhi[off] = make_uint2(packh2(hx,hy), packh2(hz,hw));
            *(uint2*)&blo[off] = make_uint2(packh2(lx,ly), packh2(lz,lw));
        }
    }
    __syncthreads();

    for (int c = 0; c < nchunks; c++) {
        if (c + 1 < nchunks) {
            int kp = kbase + (c + 1) * 32;
            #pragma unroll
            for (int j = 0; j < 4; j++) {
                stA[j] = *(const float4*)&A[(size_t)(m0 + rb + 32*j) * ldA + kp + q*4];
                if (scA) bnl4(stA[j], kp + q*4, scA, shA);
                stB[j] = *(const float4*)&B[(size_t)(n0 + rb + 32*j) * ldA + kp + q*4];
            }
        }

        const uint32_t* base = smu + (c & 1) * BUFU32;
        const uint32_t* pAhi = base;
        const uint32_t* pAlo = base + PLANE;
        const uint32_t* pBhi = base + 2*PLANE;
        const uint32_t* pBlo = base + 3*PLANE;

        #pragma unroll
        for (int ks = 0; ks < 2; ks++) {
            const int kk = ks * 8;
            uint32_t aH[4][4], aL[4][4], bH[4][2], bL[4][2];
            #pragma unroll
            for (int mt = 0; mt < 4; mt++) {
                int ro = (m0w + mt*16 + g) * PSTRIDE + kk + t;
                aH[mt][0] = pAhi[ro];
                aH[mt][1] = pAhi[ro + 8*PSTRIDE];
                aH[mt][2] = pAhi[ro + 4];
                aH[mt][3] = pAhi[ro + 8*PSTRIDE + 4];
                aL[mt][0] = pAlo[ro];
                aL[mt][1] = pAlo[ro + 8*PSTRIDE];
                aL[mt][2] = pAlo[ro + 4];
                aL[mt][3] = pAlo[ro + 8*PSTRIDE + 4];
            }
            #pragma unroll
            for (int nt = 0; nt < 4; nt++) {
                int rn = (n0w + nt*8 + g) * PSTRIDE + kk + t;
                bH[nt][0] = pBhi[rn];
                bH[nt][1] = pBhi[rn + 4];
                bL[nt][0] = pBlo[rn];
                bL[nt][1] = pBlo[rn + 4];
            }
            #pragma unroll
            for (int mt = 0; mt < 4; mt++)
                #pragma unroll
                for (int nt = 0; nt < 4; nt++) {
                    MMA_F16(accH[mt][nt], aH[mt], bH[nt]);
                    MMA_F16(accL[mt][nt], aH[mt], bL[nt]);
                    MMA_F16(accL[mt][nt], aL[mt], bH[nt]);
                }
        }

        if (c + 1 < nchunks) {
            uint32_t* bb = smu + ((c + 1) & 1) * BUFU32;
            uint32_t* ahi = bb;           uint32_t* alo = bb + PLANE;
            uint32_t* bhi = bb + 2*PLANE; uint32_t* blo = bb + 3*PLANE;
            #pragma unroll
            for (int j = 0; j < 4; j++) {
                int off = (rb + 32*j) * PSTRIDE + 2*q;
                float4 v = stA[j];
                float hx,lx,hy,ly,hz,lz,hw,lw;
                split11(v.x,hx,lx); split11(v.y,hy,ly); split11(v.z,hz,lz); split11(v.w,hw,lw);
                *(uint2*)&ahi[off] = make_uint2(packh2(hx,hy), packh2(hz,hw));
                *(uint2*)&alo[off] = make_uint2(packh2(lx,ly), packh2(lz,lw));
                v = stB[j];
                split11(v.x,hx,lx); split11(v.y,hy,ly); split11(v.z,hz,lz); split11(v.w,hw,lw);
                *(uint2*)&bhi[off] = make_uint2(packh2(hx,hy), packh2(hz,hw));
                *(uint2*)&blo[off] = make_uint2(packh2(lx,ly), packh2(lz,lw));
            }
        }
        __syncthreads();
    }

    const float inv2048 = 1.0f / 2048.0f;
    float* Cp = C + (size_t)blockIdx.z * splitStride;
    #pragma unroll
    for (int mt = 0; mt < 4; mt++) {
        #pragma unroll
        for (int nt = 0; nt < 4; nt++) {
            int row = m0 + m0w + mt*16 + g;
            int col = n0 + n0w + nt*8 + 2*t;
            float o0 = accH[mt][nt][0] + accL[mt][nt][0]*inv2048;
            float o1 = accH[mt][nt][1] + accL[mt][nt][1]*inv2048;
            float o2 = accH[mt][nt][2] + accL[mt][nt][2]*inv2048;
            float o3 = accH[mt][nt][3] + accL[mt][nt][3]*inv2048;
            if (bias) {
                float bx = bias[col], by = bias[col+1];
                o0 += bx; o1 += by; o2 += bx; o3 += by;
            }
            if (act) {
                o0 = fmaxf(o0, 0.f); o1 = fmaxf(o1, 0.f);
                o2 = fmaxf(o2, 0.f); o3 = fmaxf(o3, 0.f);
            }
            *(float2*)&Cp[(size_t)row * ldc + col] = make_float2(o0, o1);
            *(float2*)&Cp[(size_t)(row + 8) * ldc + col] = make_float2(o2, o3);
        }
    }
}

// ============================================================================
// Persistent logits GEMM: A[32768,128] @ Wfc[512,128]^T + bias, fused argmax.
// grid (4, 32): each CTA owns 128 cols, converts B ONCE, loops 8 m-tiles.
// ============================================================================
__global__ __launch_bounds__(256, 1) void gemm_logits(const float* __restrict__ A,
        const float* __restrict__ B, const float* __restrict__ bias,
        float2* __restrict__ amax) {
    extern __shared__ float smf[];
    uint32_t* smu = (uint32_t*)smf;
    float2* sred = (float2*)(smf + 16 * PLANE);
    const int tid  = threadIdx.x;
    const int lane = tid & 31;
    const int g    = lane >> 2;
    const int t    = lane & 3;
    const int warp = tid >> 5;
    const int m0w  = (warp >> 2) * 64;
    const int n0w  = (warp & 3) * 32;
    const int n0   = blockIdx.x * 128;
    const int warp_n = warp & 3;
    const int rb = tid >> 3;
    const int q  = tid & 7;
    const float inv2048 = 1.0f / 2048.0f;

    // convert B once: 4 chunks of K=32
    #pragma unroll
    for (int c = 0; c < 4; c++) {
        uint32_t* bhi = smu + (8 + c*2) * PLANE;
        uint32_t* blo = smu + (9 + c*2) * PLANE;
        #pragma unroll
        for (int j = 0; j < 4; j++) {
            int row = rb + 32*j;
            float4 v = *(const float4*)&B[(size_t)(n0 + row) * GH + c*32 + q*4];
            float hx,lx,hy,ly,hz,lz,hw,lw;
            split11(v.x,hx,lx); split11(v.y,hy,ly); split11(v.z,hz,lz); split11(v.w,hw,lw);
            int off = row * PSTRIDE + 2*q;
            *(uint2*)&bhi[off] = make_uint2(packh2(hx,hy), packh2(hz,hw));
            *(uint2*)&blo[off] = make_uint2(packh2(lx,ly), packh2(lz,lw));
        }
    }
    __syncthreads();

    for (int mi = 0; mi < 8; mi++) {
        const int m0 = (blockIdx.y * 8 + mi) * 128;

        // convert A tile (all 4 chunks)
        #pragma unroll
        for (int c = 0; c < 4; c++) {
            uint32_t* ahi = smu + (c*2) * PLANE;
            uint32_t* alo = smu + (c*2 + 1) * PLANE;
            #pragma unroll
            for (int j = 0; j < 4; j++) {
                int row = rb + 32*j;
                float4 v = *(const float4*)&A[(size_t)(m0 + row) * GH + c*32 + q*4];
                float hx,lx,hy,ly,hz,lz,hw,lw;
                split11(v.x,hx,lx); split11(v.y,hy,ly); split11(v.z,hz,lz); split11(v.w,hw,lw);
                int off = row * PSTRIDE + 2*q;
                *(uint2*)&ahi[off] = make_uint2(packh2(hx,hy), packh2(hz,hw));
                *(uint2*)&alo[off] = make_uint2(packh2(lx,ly), packh2(lz,lw));
            }
        }
        __syncthreads();

        float accH[4][4][4], accL[4][4][4];
        #pragma unroll
        for (int mt = 0; mt < 4; mt++)
            #pragma unroll
            for (int nt = 0; nt < 4; nt++)
                #pragma unroll
                for (int i = 0; i < 4; i++) { accH[mt][nt][i] = 0.f; accL[mt][nt][i] = 0.f; }

        #pragma unroll
        for (int c = 0; c < 4; c++) {
            const uint32_t* pAhi = smu + (c*2) * PLANE;
            const uint32_t* pAlo = smu + (c*2 + 1) * PLANE;
            const uint32_t* pBhi = smu + (8 + c*2) * PLANE;
            const uint32_t* pBlo = smu + (9 + c*2) * PLANE;
            #pragma unroll
            for (int ks = 0; ks < 2; ks++) {
                const int kk = ks * 8;
                uint32_t aH[4][4], aL[4][4], bH[4][2], bL[4][2];
                #pragma unroll
                for (int mt = 0; mt < 4; mt++) {
                    int ro = (m0w + mt*16 + g) * PSTRIDE + kk + t;
                    aH[mt][0] = pAhi[ro];
                    aH[mt][1] = pAhi[ro + 8*PSTRIDE];
                    aH[mt][2] = pAhi[ro + 4];
                    aH[mt][3] = pAhi[ro + 8*PSTRIDE + 4];
                    aL[mt][0] = pAlo[ro];
                    aL[mt][1] = pAlo[ro + 8*PSTRIDE];
                    aL[mt][2] = pAlo[ro + 4];
                    aL[mt][3] = pAlo[ro + 8*PSTRIDE + 4];
                }
                #pragma unroll
                for (int nt = 0; nt < 4; nt++) {
                    int rn = (n0w + nt*8 + g) * PSTRIDE + kk + t;
                    bH[nt][0] = pBhi[rn];
                    bH[nt][1] = pBhi[rn + 4];
                    bL[nt][0] = pBlo[rn];
                    bL[nt][1] = pBlo[rn + 4];
                }
                #pragma unroll
                for (int mt = 0; mt < 4; mt++)
                    #pragma unroll
                    for (int nt = 0; nt < 4; nt++) {
                        MMA_F16(accH[mt][nt], aH[mt], bH[nt]);
                        MMA_F16(accL[mt][nt], aH[mt], bL[nt]);
                        MMA_F16(accL[mt][nt], aL[mt], bH[nt]);
                    }
            }
        }

        // fused bias + per-row argmax over this CTA's 128 cols
        #pragma unroll
        for (int half = 0; half < 2; half++) {
            #pragma unroll
            for (int mt = 0; mt < 4; mt++) {
                int rloc = m0w + mt*16 + g + half*8;
                float best = -1e30f; int bidx = 0;
                #pragma unroll
                for (int nt = 0; nt < 4; nt++) {
                    #pragma unroll
                    for (int e = 0; e < 2; e++) {
                        int col = n0 + n0w + nt*8 + 2*t + e;
                        float v = accH[mt][nt][half*2 + e] + accL[mt][nt][half*2 + e]*inv2048
                                  + bias[col];
                        if (v > best) { best = v; bidx = col; }
                    }
                }
                #pragma unroll
                for (int o = 1; o < 4; o <<= 1) {
                    float ov = __shfl_xor_sync(0xffffffffu, best, o);
                    int   oi = __shfl_xor_sync(0xffffffffu, bidx, o);
                    if (ov > best || (ov == best && oi < bidx)) { best = ov; bidx = oi; }
                }
                if (t == 0) sred[rloc * 4 + warp_n] = make_float2(best, __int_as_float(bidx));
            }
        }
        __syncthreads();
        if (tid < 128) {
            float best = -1e30f; int bidx = 0x7fffffff;
            #pragma unroll
            for (int wn = 0; wn < 4; wn++) {
                float2 e = sred[tid * 4 + wn];
                int ei = __float_as_int(e.y);
                if (e.x > best || (e.x == best && ei < bidx)) { best = e.x; bidx = ei; }
            }
            amax[(size_t)(m0 + tid) * 4 + blockIdx.x] = make_float2(best, __int_as_float(bidx));
        }
        __syncthreads();
    }
}

// generic deterministic split-K reduce + bias (+optional relu)
__global__ __launch_bounds__(256) void reduce_gen(const float* __restrict__ ws,
        const float* __restrict__ bias, float* __restrict__ out,
        int nsplit, int strideElems, int nmask, int act) {
    int i = blockIdx.x * 256 + threadIdx.x;
    float s = 0.0f;
    for (int sp = 0; sp < nsplit; sp++) s += ws[(size_t)sp * strideElems + i];
    s += bias[i & nmask];
    if (act) s = fmaxf(s, 0.f);
    out[i] = s;
}

// ============================================================================
// BatchNorm stats, two-stage
// ============================================================================
__global__ void bn_part(const float* __restrict__ h, float* __restrict__ ps,
                        float* __restrict__ pss, int N) {
    int f = blockIdx.x * 256 + threadIdx.x;
    int part = blockIdx.y;
    float s = 0.f, ss = 0.f;
    int b0 = part * 32;
    #pragma unroll 4
    for (int b = b0; b < b0 + 32; b++) {
        float v = h[(size_t)b * N + f];
        s += v; ss += v * v;
    }
    ps[part * N + f] = s;
    pss[part * N + f] = ss;
}

__global__ void bn_final(const float* __restrict__ ps, const float* __restrict__ pss,
                         const float* __restrict__ g, const float* __restrict__ be,
                         float* __restrict__ scale, float* __restrict__ shift, int N) {
    int f = blockIdx.x * 256 + threadIdx.x;
    float s = 0.f, ss = 0.f;
    #pragma unroll
    for (int p = 0; p < 8; p++) { s += ps[p * N + f]; ss += pss[p * N + f]; }
    float mean = s * (1.0f / BATCH);
    float var = ss * (1.0f / BATCH) - mean * mean;
    float sc = rsqrtf(var + 1e-5f) * g[f];
    scale[f] = sc;
    shift[f] = be[f] - mean * sc;
}

// ============================================================================
// fp32x2 GEMM for small layers; dual-output via blockIdx.z
// ============================================================================
__device__ __forceinline__ void fma2(ull &d, ull a, ull b) {
    asm("fma.rn.f32x2 %0, %1, %2, %0;" : "+l"(d) : "l"(a), "l"(b));
}
__device__ __forceinline__ ull pk2(float x, float y) {
    ull d; asm("mov.b64 %0, {%1, %2};" : "=l"(d) : "f"(x), "f"(y)); return d;
}
__device__ __forceinline__ float2 unpk2(ull d) {
    float2 r; asm("mov.b64 {%0, %1}, %2;" : "=f"(r.x), "=f"(r.y) : "l"(d)); return r;
}

__global__ __launch_bounds__(256) void gemm_kernel(const float* __restrict__ A,
        const float* __restrict__ W, const float* __restrict__ bias,
        float* __restrict__ C, int M, int N, int K, int act,
        const float* __restrict__ W2, const float* __restrict__ b2,
        float* __restrict__ C2) {
    if (blockIdx.z == 1) { W = W2; bias = b2; C = C2; }
    __shared__ float As[16][68];
    __shared__ float Bs[16][68];
    const int tid = threadIdx.x;
    const int n0 = blockIdx.x * 64;
    const int m0 = blockIdx.y * 64;
    const int trow = tid >> 4;
    const int tcol = tid & 15;
    const int lm = tid >> 2;
    const int lk = (tid & 3) * 4;

    ull acc[4][2];
    #pragma unroll
    for (int r = 0; r < 4; r++) { acc[r][0] = 0ull; acc[r][1] = 0ull; }

    for (int kk = 0; kk < K; kk += 16) {
        float4 va = *(const float4*)&A[(size_t)(m0 + lm) * K + kk + lk];
        float4 vb = *(const float4*)&W[(size_t)(n0 + lm) * K + kk + lk];
        As[lk+0][lm] = va.x; As[lk+1][lm] = va.y; As[lk+2][lm] = va.z; As[lk+3][lm] = va.w;
        Bs[lk+0][lm] = vb.x; Bs[lk+1][lm] = vb.y; Bs[lk+2][lm] = vb.z; Bs[lk+3][lm] = vb.w;
        __syncthreads();
        #pragma unroll
        for (int k = 0; k < 16; k++) {
            float4 a = *(const float4*)&As[k][trow * 4];
            const ull* bp = (const ull*)&Bs[k][tcol * 4];
            ull b0 = bp[0], b1 = bp[1];
            ull a0 = pk2(a.x, a.x), a1 = pk2(a.y, a.y);
            ull a2 = pk2(a.z, a.z), a3 = pk2(a.w, a.w);
            fma2(acc[0][0], a0, b0); fma2(acc[0][1], a0, b1);
            fma2(acc[1][0], a1, b0); fma2(acc[1][1], a1, b1);
            fma2(acc[2][0], a2, b0); fma2(acc[2][1], a2, b1);
            fma2(acc[3][0], a3, b0); fma2(acc[3][1], a3, b1);
        }
        __syncthreads();
    }

    #pragma unroll
    for (int r = 0; r < 4; r++) {
        int m = m0 + trow * 4 + r;
        int n = n0 + tcol * 4;
        float2 v0 = unpk2(acc[r][0]);
        float2 v1 = unpk2(acc[r][1]);
        float o0 = v0.x + bias[n+0];
        float o1 = v0.y + bias[n+1];
        float o2 = v1.x + bias[n+2];
        float o3 = v1.y + bias[n+3];
        if (act == 1) {
            o0 = fmaxf(o0, 0.f); o1 = fmaxf(o1, 0.f);
            o2 = fmaxf(o2, 0.f); o3 = fmaxf(o3, 0.f);
        }
        *(float4*)&C[(size_t)m * N + n] = make_float4(o0, o1, o2, o3);
    }
}

// ============================================================================
// reparameterize + emit mu/logvar to output tail
// ============================================================================
__global__ void reparam_kernel(const float* __restrict__ mu, const float* __restrict__ lv,
                               const float* __restrict__ eps, float* __restrict__ z,
                               float* __restrict__ out) {
    int i = blockIdx.x * 256 + threadIdx.x;
    float m = mu[i], l = lv[i];
    z[i] = m + eps[i] * expf(0.5f * l);
    out[OFF_MU + i] = m;
    out[OFF_LV + i] = l;
}

// ============================================================================
// GRU recurrence: 128 CTAs x 384 thr, 2 rows/CTA, register weights + f32x2
// ============================================================================
__global__ __launch_bounds__(384, 1) void gru_kernel(const float* __restrict__ xp,
        const float* __restrict__ Whh, const float* __restrict__ bhh,
        float* __restrict__ h2all) {
    __shared__ __align__(16) float h_a[128];
    __shared__ __align__(16) float h_b[128];
    __shared__ float hp_s[768];
    __shared__ float xp_s[768];
    const int j = threadIdx.x;
    const int row0 = blockIdx.x * 2;

    ull w2[64];
    #pragma unroll
    for (int kq = 0; kq < 32; kq++) {
        float4 v = *(const float4*)&Whh[(size_t)j * GH + kq * 4];
        w2[2*kq+0] = pk2(v.x, v.y);
        w2[2*kq+1] = pk2(v.z, v.w);
    }
    const float bh = bhh[j];
    xp_s[j]       = xp[(size_t)row0 * 384 + j];
    xp_s[384 + j] = xp[(size_t)(row0 + 1) * 384 + j];
    if (j < 128) { h_a[j] = 0.0f; h_b[j] = 0.0f; }
    __syncthreads();

    for (int t = 0; t < SEQ; t++) {
        ull accA = 0ull, accB = 0ull;
        #pragma unroll
        for (int kq = 0; kq < 32; kq++) {
            ulonglong2 ha = *(const ulonglong2*)&h_a[kq * 4];
            ulonglong2 hb = *(const ulonglong2*)&h_b[kq * 4];
            fma2(accA, w2[2*kq+0], ha.x);
            fma2(accA, w2[2*kq+1], ha.y);
            fma2(accB, w2[2*kq+0], hb.x);
            fma2(accB, w2[2*kq+1], hb.y);
        }
        float2 pa = unpk2(accA);
        float2 pb = unpk2(accB);
        hp_s[j]       = pa.x + pa.y + bh;
        hp_s[384 + j] = pb.x + pb.y + bh;
        __syncthreads();
        if (j < 256) {
            int r = j >> 7, u = j & 127;
            const float* hp = hp_s + r * 384;
            const float* xq = xp_s + r * 384;
            float rg = 1.0f / (1.0f + expf(-(xq[u]       + hp[u])));
            float zg = 1.0f / (1.0f + expf(-(xq[128 + u] + hp[128 + u])));
            float nn = tanhf(xq[256 + u] + rg * hp[256 + u]);
            float hold = r ? h_b[u] : h_a[u];
            float hnew = (1.0f - zg) * nn + zg * hold;
            if (r) h_b[u] = hnew; else h_a[u] = hnew;
            h2all[((size_t)t * BATCH + row0 + r) * GH + u] = hnew;
        }
        __syncthreads();
    }
}

// ============================================================================
// final argmax reduce over 4 partials + one-hot write
// ============================================================================
__global__ __launch_bounds__(256) void argmax_final(const float2* __restrict__ amp,
                                                    float* __restrict__ out) {
    int row  = blockIdx.x * 8 + (threadIdx.x >> 5);
    int lane = threadIdx.x & 31;
    float best = -1e30f; int bi = 0x7fffffff;
    if (lane < 4) {
        float2 e = amp[(size_t)row * 4 + lane];
        best = e.x; bi = __float_as_int(e.y);
    }
    #pragma unroll
    for (int o = 1; o < 4; o <<= 1) {
        float ov = __shfl_xor_sync(0xffffffffu, best, o);
        int   oi = __shfl_xor_sync(0xffffffffu, bi, o);
        if (ov > best || (ov == best && oi < bi)) { best = ov; bi = oi; }
    }
    bi = __shfl_sync(0xffffffffu, bi, 0);
    int t = row >> 8, b = row & 255;
    float* op = out + (size_t)b * (SEQ * VOCAB) + (size_t)t * VOCAB;
    #pragma unroll
    for (int q = 0; q < 4; q++) {
        int c = lane * 16 + q * 4;
        *(float4*)&op[c] = make_float4(c == bi ? 1.f : 0.f, c + 1 == bi ? 1.f : 0.f,
                                       c + 2 == bi ? 1.f : 0.f, c + 3 == bi ? 1.f : 0.f);
    }
}

// ============================================================================
// launcher
// ============================================================================
extern "C" void kernel_launch(void* const* d_in, const int* in_sizes, int n_in,
                              void* d_out, int out_size) {
    (void)in_sizes; (void)n_in; (void)out_size;
    const float* x    = (const float*)d_in[0];
    const float* eps  = (const float*)d_in[1];
    const float* W0   = (const float*)d_in[2];
    const float* b0   = (const float*)d_in[3];
    const float* g0   = (const float*)d_in[4];
    const float* be0  = (const float*)d_in[5];
    const float* W1   = (const float*)d_in[6];
    const float* b1   = (const float*)d_in[7];
    const float* g1   = (const float*)d_in[8];
    const float* be1  = (const float*)d_in[9];
    const float* W2   = (const float*)d_in[10];
    const float* b2   = (const float*)d_in[11];
    const float* g2   = (const float*)d_in[12];
    const float* be2  = (const float*)d_in[13];
    const float* Wout = (const float*)d_in[14];
    const float* bout = (const float*)d_in[15];
    const float* Wmu  = (const float*)d_in[16];
    const float* bmu  = (const float*)d_in[17];
    const float* Wlv  = (const float*)d_in[18];
    const float* blv  = (const float*)d_in[19];
    const float* Wih  = (const float*)d_in[20];
    const float* bih  = (const float*)d_in[21];
    const float* Whh  = (const float*)d_in[22];
    const float* bhh  = (const float*)d_in[23];
    const float* Wfc  = (const float*)d_in[24];
    const float* bfc  = (const float*)d_in[25];
    float* out = (float*)d_out;

    float* S = nullptr;
    cudaGetSymbolAddress((void**)&S, g_scratch);

    cudaFuncSetAttribute(gemm_mma, cudaFuncAttributeMaxDynamicSharedMemorySize, MMA_SMEM);
    cudaFuncSetAttribute(gemm_logits, cudaFuncAttributeMaxDynamicSharedMemorySize, LOGITS_SMEM);

    // --- encoder layer 0: fp16-split mma, split-K=9 (144 CTAs = 1 wave) ---
    gemm_mma<<<dim3(8, 2, GSPLITS), 256, MMA_SMEM>>>(x, W0, nullptr, S + S_WS,
        K0, N0, TCHUNKS0, GSPLITS, (size_t)BATCH * N0, nullptr, nullptr, 0);
    reduce_gen<<<1024, 256>>>(S + S_WS, b0, S + S_H0, GSPLITS, BATCH * N0, N0 - 1, 0);
    bn_part<<<dim3(4, 8), 256>>>(S + S_H0, S + S_BNP, S + S_BNQ, 1024);
    bn_final<<<4, 256>>>(S + S_BNP, S + S_BNQ, g0, be0, S + S_SCALE, S + S_SHIFT, 1024);

    // --- encoder layer 1: 1024 -> 512, mma split-K=16 (BN0+lrelu fused on A) ---
    gemm_mma<<<dim3(4, 2, 16), 256, MMA_SMEM>>>(S + S_H0, W1, nullptr, S + S_WS,
        1024, 512, 32, 16, (size_t)BATCH * 512, S + S_SCALE, S + S_SHIFT, 0);
    reduce_gen<<<512, 256>>>(S + S_WS, b1, S + S_H1, 16, BATCH * 512, 511, 0);
    bn_part<<<dim3(2, 8), 256>>>(S + S_H1, S + S_BNP, S + S_BNQ, 512);
    bn_final<<<2, 256>>>(S + S_BNP, S + S_BNQ, g1, be1, S + S_SCALE, S + S_SHIFT, 512);

    // --- encoder layer 2: 512 -> 256, mma split-K=8 (BN1 fused) ---
    gemm_mma<<<dim3(2, 2, 8), 256, MMA_SMEM>>>(S + S_H1, W2, nullptr, S + S_WS,
        512, 256, 16, 8, (size_t)BATCH * 256, S + S_SCALE, S + S_SHIFT, 0);
    reduce_gen<<<256, 256>>>(S + S_WS, b2, S + S_H2B, 8, BATCH * 256, 255, 0);
    bn_part<<<dim3(1, 8), 256>>>(S + S_H2B, S + S_BNP, S + S_BNQ, 256);
    bn_final<<<1, 256>>>(S + S_BNP, S + S_BNQ, g2, be2, S + S_SCALE, S + S_SHIFT, 256);

    // --- out layer: 256 -> 128, mma split-K=8 (BN2 fused), relu in reduce ---
    gemm_mma<<<dim3(1, 2, 8), 256, MMA_SMEM>>>(S + S_H2B, Wout, nullptr, S + S_WS,
        256, 128, 8, 8, (size_t)BATCH * 128, S + S_SCALE, S + S_SHIFT, 0);
    reduce_gen<<<128, 256>>>(S + S_WS, bout, S + S_HENC, 8, BATCH * 128, 127, 1);

    // --- mu & logvar in one dual-output launch ---
    gemm_kernel<<<dim3(2, 4, 2), 256>>>(S + S_HENC, Wmu, bmu, S + S_MU, 256, 128, 128, 0,
                                        Wlv, blv, S + S_LV);

    // --- reparameterize ---
    reparam_kernel<<<128, 256>>>(S + S_MU, S + S_LV, eps, S + S_Z, out);

    // --- GRU input projection ---
    gemm_kernel<<<dim3(6, 4, 1), 256>>>(S + S_Z, Wih, bih, S + S_XP, 256, 384, 128, 0,
                                        nullptr, nullptr, nullptr);

    // --- GRU recurrence ---
    gru_kernel<<<128, 384>>>(S + S_XP, Whh, bhh, S + S_H2ALL);

    // --- persistent logits GEMM with fused bias+argmax (1 wave) ---
    gemm_logits<<<dim3(4, 32), 256, LOGITS_SMEM>>>(S + S_H2ALL, Wfc, bfc,
                                                   (float2*)(S + S_AMP));
    argmax_final<<<4096, 256>>>((const float2*)(S + S_AMP), out);
}